// round 1
// baseline (speedup 1.0000x reference)
#include <cuda_runtime.h>

// Problem constants
#define B_    16
#define T_    64
#define C_    512
#define S_    4096
#define INNER 512
#define DIMH  64
#define NHEAD 8
// SCALE = 64^-0.5 = 0.125

// Scratch (device globals; no allocations allowed)
__device__ float g_q [B_ * T_ * INNER];          // (B,T,inner)   2 MB
__device__ float g_k [(long)B_ * INNER * S_];    // (B,inner,S) 128 MB
__device__ float g_v [(long)B_ * INNER * S_];    // (B,inner,S) 128 MB
__device__ float g_ao[B_ * T_ * INNER];          // (B,T,inner)   2 MB

// ---------------------------------------------------------------------------
// SGEMM: C[M,N] = A[M,K] * op(B)
//   BT=false: B is row-major [K,N]  (NN)   -- used for k/v projections
//   BT=true : B is row-major [N,K]  (NT)   -- used for q / output projections
// 128x128 block tile, Ktile=8, 256 threads, 8x8 per-thread microtile in
// 2x2 quadrants of 4x4 (conflict-free float4 smem reads). Register prefetch
// of the next K-slice overlaps gmem latency with FMA.
// blockIdx.z batches B and C (A is shared across batches in our uses).
// ---------------------------------------------------------------------------
template <bool BT>
__global__ __launch_bounds__(256, 2)
void sgemm_kernel(const float* __restrict__ A, const float* __restrict__ B,
                  float* __restrict__ C, int M, int N, int K,
                  long bBatch, long cBatch)
{
    const float* Bb = B + (long)blockIdx.z * bBatch;
    float*       Cb = C + (long)blockIdx.z * cBatch;

    __shared__ float As[8][132];
    __shared__ float Bs[8][132];

    const int tid  = threadIdx.x;
    const int tx   = tid & 15;       // 0..15  (N dir)
    const int ty   = tid >> 4;       // 0..15  (M dir)
    const int m0   = blockIdx.y * 128;
    const int n0   = blockIdx.x * 128;
    const int lrow = tid >> 1;       // 0..127
    const int lcol = (tid & 1) * 4;  // 0 or 4

    float acc[2][2][4][4];
    #pragma unroll
    for (int qm = 0; qm < 2; qm++)
        #pragma unroll
        for (int qn = 0; qn < 2; qn++)
            #pragma unroll
            for (int i = 0; i < 4; i++)
                #pragma unroll
                for (int j = 0; j < 4; j++)
                    acc[qm][qn][i][j] = 0.f;

    const int kIter = K >> 3;

    // first slice prefetch
    float4 av = *(const float4*)&A[(long)(m0 + lrow) * K + lcol];
    float4 bv;
    if (BT) bv = *(const float4*)&Bb[(long)(n0 + lrow) * K + lcol];
    else    bv = *(const float4*)&Bb[(long)(tid >> 5) * N + n0 + (tid & 31) * 4];

    for (int it = 0; it < kIter; ++it) {
        __syncthreads();   // previous compute done before smem overwrite
        As[lcol + 0][lrow] = av.x;
        As[lcol + 1][lrow] = av.y;
        As[lcol + 2][lrow] = av.z;
        As[lcol + 3][lrow] = av.w;
        if (BT) {
            Bs[lcol + 0][lrow] = bv.x;
            Bs[lcol + 1][lrow] = bv.y;
            Bs[lcol + 2][lrow] = bv.z;
            Bs[lcol + 3][lrow] = bv.w;
        } else {
            *(float4*)&Bs[tid >> 5][(tid & 31) * 4] = bv;
        }
        __syncthreads();

        // prefetch next slice (overlaps with FMA below)
        if (it + 1 < kIter) {
            const int k0 = (it + 1) << 3;
            av = *(const float4*)&A[(long)(m0 + lrow) * K + k0 + lcol];
            if (BT) bv = *(const float4*)&Bb[(long)(n0 + lrow) * K + k0 + lcol];
            else    bv = *(const float4*)&Bb[(long)(k0 + (tid >> 5)) * N + n0 + (tid & 31) * 4];
        }

        #pragma unroll
        for (int kk = 0; kk < 8; kk++) {
            float4 a0 = *(const float4*)&As[kk][ty * 4];
            float4 a1 = *(const float4*)&As[kk][64 + ty * 4];
            float4 b0 = *(const float4*)&Bs[kk][tx * 4];
            float4 b1 = *(const float4*)&Bs[kk][64 + tx * 4];
            float ar[2][4] = {{a0.x, a0.y, a0.z, a0.w}, {a1.x, a1.y, a1.z, a1.w}};
            float br[2][4] = {{b0.x, b0.y, b0.z, b0.w}, {b1.x, b1.y, b1.z, b1.w}};
            #pragma unroll
            for (int qm = 0; qm < 2; qm++)
                #pragma unroll
                for (int i = 0; i < 4; i++)
                    #pragma unroll
                    for (int qn = 0; qn < 2; qn++)
                        #pragma unroll
                        for (int j = 0; j < 4; j++)
                            acc[qm][qn][i][j] += ar[qm][i] * br[qn][j];
        }
    }

    #pragma unroll
    for (int qm = 0; qm < 2; qm++)
        #pragma unroll
        for (int i = 0; i < 4; i++) {
            const long row = m0 + qm * 64 + ty * 4 + i;
            #pragma unroll
            for (int qn = 0; qn < 2; qn++) {
                float4 w = make_float4(acc[qm][qn][i][0], acc[qm][qn][i][1],
                                       acc[qm][qn][i][2], acc[qm][qn][i][3]);
                *(float4*)&Cb[row * N + n0 + qn * 64 + tx * 4] = w;
            }
        }
}

// ---------------------------------------------------------------------------
// Fused attention: one block per (b, head). Online softmax over S in tiles of
// 128. Each thread owns one t-row (t = tid>>2) and a 32-wide contiguous s
// chunk (sc = tid&3); q row and the 64-wide output accumulator live in
// registers; K/V tiles staged in dynamic smem.
// Layouts: g_q/g_ao (B,T,inner) with channel = h*64+d; g_k/g_v (B,inner,S).
// ---------------------------------------------------------------------------
#define ATTN_SMEM ((2 * 64 * 128 + 64 * 65) * 4)

__global__ __launch_bounds__(256, 1)
void attn_kernel(const float* __restrict__ gq, const float* __restrict__ gk,
                 const float* __restrict__ gv, float* __restrict__ go)
{
    extern __shared__ float sm[];
    float* Ks = sm;              // 64 x 128
    float* Vs = sm + 64 * 128;   // 64 x 128
    float* Qs = sm + 2 * 64 * 128; // 64 x 65 (padded)

    const int bh = blockIdx.x;
    const int b  = bh >> 3;
    const int h  = bh & 7;
    const int tid = threadIdx.x;
    const int t  = tid >> 2;     // row 0..63
    const int sc = tid & 3;      // s-chunk 0..3
    const int sb = sc * 32;      // s offset within tile

    // stage q (pre-scaled)
    const float* qb = gq + ((long)b * T_) * INNER + h * DIMH;
    for (int i = tid; i < T_ * 16; i += 256) {
        const int r = i >> 4, c = (i & 15) << 2;
        float4 qv = *(const float4*)&qb[(long)r * INNER + c];
        Qs[r * 65 + c + 0] = qv.x * 0.125f;
        Qs[r * 65 + c + 1] = qv.y * 0.125f;
        Qs[r * 65 + c + 2] = qv.z * 0.125f;
        Qs[r * 65 + c + 3] = qv.w * 0.125f;
    }
    __syncthreads();

    float q_r[64];
    #pragma unroll
    for (int d = 0; d < 64; d++) q_r[d] = Qs[t * 65 + d];

    float acc[64];
    #pragma unroll
    for (int d = 0; d < 64; d++) acc[d] = 0.f;
    float m_run = -3.0e38f;
    float l_run = 0.f;

    const long  kvoff = ((long)b * INNER + h * DIMH) * S_;
    const float* kb = gk + kvoff;
    const float* vb = gv + kvoff;

    for (int s0 = 0; s0 < S_; s0 += 128) {
        __syncthreads();   // previous tile fully consumed
        for (int i = tid; i < 64 * 32; i += 256) {
            const int d = i >> 5, c = (i & 31) << 2;
            *(float4*)&Ks[d * 128 + c] = *(const float4*)&kb[(long)d * S_ + s0 + c];
            *(float4*)&Vs[d * 128 + c] = *(const float4*)&vb[(long)d * S_ + s0 + c];
        }
        __syncthreads();

        // scores for this thread's 32 s values
        float4 scr[8];
        #pragma unroll
        for (int j = 0; j < 8; j++) scr[j] = make_float4(0.f, 0.f, 0.f, 0.f);
        #pragma unroll
        for (int d = 0; d < 64; d++) {
            const float qd = q_r[d];
            const float4* kr = (const float4*)&Ks[d * 128 + sb];
            #pragma unroll
            for (int j = 0; j < 8; j++) {
                float4 k4 = kr[j];
                scr[j].x += qd * k4.x;
                scr[j].y += qd * k4.y;
                scr[j].z += qd * k4.z;
                scr[j].w += qd * k4.w;
            }
        }

        // row max across the 4 lanes of this row
        float mt = -3.0e38f;
        #pragma unroll
        for (int j = 0; j < 8; j++) {
            mt = fmaxf(mt, fmaxf(fmaxf(scr[j].x, scr[j].y), fmaxf(scr[j].z, scr[j].w)));
        }
        mt = fmaxf(mt, __shfl_xor_sync(0xffffffffu, mt, 1));
        mt = fmaxf(mt, __shfl_xor_sync(0xffffffffu, mt, 2));
        const float m_new = fmaxf(m_run, mt);
        const float corr  = __expf(m_run - m_new);

        float ls = 0.f;
        #pragma unroll
        for (int j = 0; j < 8; j++) {
            scr[j].x = __expf(scr[j].x - m_new);
            scr[j].y = __expf(scr[j].y - m_new);
            scr[j].z = __expf(scr[j].z - m_new);
            scr[j].w = __expf(scr[j].w - m_new);
            ls += scr[j].x + scr[j].y + scr[j].z + scr[j].w;
        }
        ls += __shfl_xor_sync(0xffffffffu, ls, 1);
        ls += __shfl_xor_sync(0xffffffffu, ls, 2);
        l_run = l_run * corr + ls;
        m_run = m_new;

        #pragma unroll
        for (int d = 0; d < 64; d++) acc[d] *= corr;

        // acc[d] += sum_s p[s] * V[d][s]
        #pragma unroll
        for (int d = 0; d < 64; d++) {
            const float4* vr = (const float4*)&Vs[d * 128 + sb];
            float a = acc[d];
            #pragma unroll
            for (int j = 0; j < 8; j++) {
                float4 v4 = vr[j];
                a += scr[j].x * v4.x;
                a += scr[j].y * v4.y;
                a += scr[j].z * v4.z;
                a += scr[j].w * v4.w;
            }
            acc[d] = a;
        }
    }

    // combine the 4 s-chunk lanes, normalize, write
    const float inv = 1.f / l_run;
    #pragma unroll
    for (int d = 0; d < 64; d++) {
        float a = acc[d];
        a += __shfl_xor_sync(0xffffffffu, a, 1);
        a += __shfl_xor_sync(0xffffffffu, a, 2);
        acc[d] = a * inv;
    }
    if (sc == 0) {
        float* ob = go + ((long)(b * T_ + t)) * INNER + h * DIMH;
        #pragma unroll
        for (int j = 0; j < 16; j++) {
            float4 w = make_float4(acc[4 * j + 0], acc[4 * j + 1],
                                   acc[4 * j + 2], acc[4 * j + 3]);
            *(float4*)&ob[4 * j] = w;
        }
    }
}

// ---------------------------------------------------------------------------
extern "C" void kernel_launch(void* const* d_in, const int* in_sizes, int n_in,
                              void* d_out, int out_size)
{
    const float* vis  = (const float*)d_in[0]; // (B,C,H,W) = (B,C,S)
    const float* lang = (const float*)d_in[1]; // (B,T,C)
    // d_in[2] = mask (unused)
    const float* Wq   = (const float*)d_in[3]; // (inner,C)
    const float* Wk   = (const float*)d_in[4];
    const float* Wv   = (const float*)d_in[5];
    const float* Wo   = (const float*)d_in[6]; // (C,inner)
    float* out = (float*)d_out;

    float *q, *k, *v, *ao;
    cudaGetSymbolAddress((void**)&q,  g_q);
    cudaGetSymbolAddress((void**)&k,  g_k);
    cudaGetSymbolAddress((void**)&v,  g_v);
    cudaGetSymbolAddress((void**)&ao, g_ao);

    cudaFuncSetAttribute(attn_kernel, cudaFuncAttributeMaxDynamicSharedMemorySize,
                         ATTN_SMEM);

    const dim3 blk(256);

    // q projection: (B*T,inner) = lang(1024,512) @ Wq^T(512,512)
    sgemm_kernel<true><<<dim3(INNER / 128, (B_ * T_) / 128, 1), blk>>>(
        lang, Wq, q, B_ * T_, INNER, C_, 0, 0);

    // k,v projections (per batch): (inner,S) = W(512,512) @ vis_b(512,4096)
    sgemm_kernel<false><<<dim3(S_ / 128, INNER / 128, B_), blk>>>(
        Wk, vis, k, INNER, S_, C_, (long)C_ * S_, (long)INNER * S_);
    sgemm_kernel<false><<<dim3(S_ / 128, INNER / 128, B_), blk>>>(
        Wv, vis, v, INNER, S_, C_, (long)C_ * S_, (long)INNER * S_);

    // fused attention: one block per (b, head)
    attn_kernel<<<B_ * NHEAD, 256, ATTN_SMEM>>>(q, k, v, ao);

    // output projection: (B*T,C) = ao(1024,512) @ Wo^T(512,512)
    sgemm_kernel<true><<<dim3(C_ / 128, (B_ * T_) / 128, 1), blk>>>(
        ao, Wo, out, B_ * T_, C_, INNER, 0, 0);
}

// round 3
// speedup vs baseline: 1.2356x; 1.2356x over previous
#include <cuda_runtime.h>

// Problem constants
#define B_    16
#define T_    64
#define C_    512
#define S_    4096
#define INNER 512
#define DIMH  64
#define NHEAD 8
// SCALE = 64^-0.5 = 0.125

// Scratch (device globals; no allocations allowed)
__device__ float g_q  [B_ * T_ * INNER];              // (B,T,inner)
__device__ float g_kv [(long)B_ * 2 * INNER * S_];    // (B, [k;v] 1024, S) 256 MB
__device__ float g_ao [B_ * T_ * INNER];              // (B,T,inner)
__device__ float g_wkv[2 * INNER * C_];               // concat(Wk,Wv), tf32-rounded

__device__ __forceinline__ float f2tf32(float x) {
    unsigned r;
    asm("cvt.rna.tf32.f32 %0, %1;" : "=r"(r) : "f"(x));
    return __uint_as_float(r);
}

// ---------------------------------------------------------------------------
// prep: concat Wk,Wv -> g_wkv with tf32 rounding (round-to-nearest; truncation
// would introduce a ~2^-10 systematic bias on every product).
// ---------------------------------------------------------------------------
__global__ void prep_wkv(const float* __restrict__ Wk, const float* __restrict__ Wv,
                         float* __restrict__ Wkv)
{
    const int i = blockIdx.x * 256 + threadIdx.x;   // 0 .. 262143
    Wkv[i]                 = f2tf32(Wk[i]);
    Wkv[INNER * C_ + i]    = f2tf32(Wv[i]);
}

// ---------------------------------------------------------------------------
// Fused k/v projection, tf32 tensor-core GEMM.
//   C[b][m][n] = sum_k A[m][k] * vis[b][k][n],  M=1024 (k rows then v rows),
//   N=4096, K=512.  A is pre-rounded tf32; vis rounded at smem-staging time.
// 128x128x16 tile, 256 threads, 8 warps as 4(m) x 2(n) -> 32x64 warp tile.
// mma.sync.aligned.m16n8k8.row.col.f32.tf32.tf32.f32.
// Smem row stride 136 floats: frag address = k*136 + m -> bank = (8k+m)%32,
// conflict-free for the (k=lane&3, m=lane>>2) fragment pattern.
// ---------------------------------------------------------------------------
#define GBM 128
#define GBN 128
#define GBK 16
#define GSTRIDE 136

__global__ __launch_bounds__(256, 2)
void gemm_kv(const float* __restrict__ A,    // g_wkv [1024][512]
             const float* __restrict__ Bg,   // vis   [16][512][4096]
             float* __restrict__ Ckv)        // g_kv  [16][1024][4096]
{
    const int b  = blockIdx.z;
    const int m0 = blockIdx.y * GBM;
    const int n0 = blockIdx.x * GBN;
    const float* Bb = Bg  + (long)b * C_ * S_;
    float*       Cb = Ckv + (long)b * 2 * INNER * S_;

    __shared__ float As[2][GBK][GSTRIDE];
    __shared__ float Bs[2][GBK][GSTRIDE];

    const int tid  = threadIdx.x;
    const int warp = tid >> 5;
    const int lane = tid & 31;
    const int wm   = (warp >> 1) * 32;   // warp m offset (0,32,64,96)
    const int wn   = (warp & 1) * 64;    // warp n offset (0,64)
    const int g    = lane >> 2;          // 0..7
    const int tg   = lane & 3;           // 0..3

    // global-load assignments
    const int ar = tid >> 1;             // A row 0..127
    const int ac = (tid & 1) * 8;        // A col 0 or 8
    const int br = tid >> 4;             // B row 0..15
    const int bc = (tid & 15) * 8;       // B col 0..120

    float acc[2][8][4];
    #pragma unroll
    for (int mt = 0; mt < 2; mt++)
        #pragma unroll
        for (int nt = 0; nt < 8; nt++)
            #pragma unroll
            for (int i = 0; i < 4; i++)
                acc[mt][nt][i] = 0.f;

    const int nIter = C_ / GBK;          // 32

    // prefetch iter 0
    float4 av0 = *(const float4*)&A [(long)(m0 + ar) * C_ + ac];
    float4 av1 = *(const float4*)&A [(long)(m0 + ar) * C_ + ac + 4];
    float4 bv0 = *(const float4*)&Bb[(long)br * S_ + n0 + bc];
    float4 bv1 = *(const float4*)&Bb[(long)br * S_ + n0 + bc + 4];

    // store iter 0 into buf 0
    As[0][ac + 0][ar] = av0.x; As[0][ac + 1][ar] = av0.y;
    As[0][ac + 2][ar] = av0.z; As[0][ac + 3][ar] = av0.w;
    As[0][ac + 4][ar] = av1.x; As[0][ac + 5][ar] = av1.y;
    As[0][ac + 6][ar] = av1.z; As[0][ac + 7][ar] = av1.w;
    {
        float4 t0 = make_float4(f2tf32(bv0.x), f2tf32(bv0.y), f2tf32(bv0.z), f2tf32(bv0.w));
        float4 t1 = make_float4(f2tf32(bv1.x), f2tf32(bv1.y), f2tf32(bv1.z), f2tf32(bv1.w));
        *(float4*)&Bs[0][br][bc]     = t0;
        *(float4*)&Bs[0][br][bc + 4] = t1;
    }

    for (int it = 0; it < nIter; ++it) {
        const int c = it & 1;
        __syncthreads();

        if (it + 1 < nIter) {
            const int k0 = (it + 1) * GBK;
            av0 = *(const float4*)&A [(long)(m0 + ar) * C_ + k0 + ac];
            av1 = *(const float4*)&A [(long)(m0 + ar) * C_ + k0 + ac + 4];
            bv0 = *(const float4*)&Bb[(long)(k0 + br) * S_ + n0 + bc];
            bv1 = *(const float4*)&Bb[(long)(k0 + br) * S_ + n0 + bc + 4];
        }

        #pragma unroll
        for (int ks = 0; ks < 2; ks++) {
            const int kb = ks * 8;
            unsigned bf[8][2];
            #pragma unroll
            for (int nt = 0; nt < 8; nt++) {
                bf[nt][0] = __float_as_uint(Bs[c][kb + tg]    [wn + nt * 8 + g]);
                bf[nt][1] = __float_as_uint(Bs[c][kb + tg + 4][wn + nt * 8 + g]);
            }
            #pragma unroll
            for (int mt = 0; mt < 2; mt++) {
                const int mrow = wm + mt * 16 + g;
                unsigned a0 = __float_as_uint(As[c][kb + tg]    [mrow]);
                unsigned a1 = __float_as_uint(As[c][kb + tg]    [mrow + 8]);
                unsigned a2 = __float_as_uint(As[c][kb + tg + 4][mrow]);
                unsigned a3 = __float_as_uint(As[c][kb + tg + 4][mrow + 8]);
                #pragma unroll
                for (int nt = 0; nt < 8; nt++) {
                    asm volatile(
                        "mma.sync.aligned.m16n8k8.row.col.f32.tf32.tf32.f32 "
                        "{%0,%1,%2,%3}, {%4,%5,%6,%7}, {%8,%9}, {%0,%1,%2,%3};"
                        : "+f"(acc[mt][nt][0]), "+f"(acc[mt][nt][1]),
                          "+f"(acc[mt][nt][2]), "+f"(acc[mt][nt][3])
                        : "r"(a0), "r"(a1), "r"(a2), "r"(a3),
                          "r"(bf[nt][0]), "r"(bf[nt][1]));
                }
            }
        }

        if (it + 1 < nIter) {
            const int n = (it + 1) & 1;
            As[n][ac + 0][ar] = av0.x; As[n][ac + 1][ar] = av0.y;
            As[n][ac + 2][ar] = av0.z; As[n][ac + 3][ar] = av0.w;
            As[n][ac + 4][ar] = av1.x; As[n][ac + 5][ar] = av1.y;
            As[n][ac + 6][ar] = av1.z; As[n][ac + 7][ar] = av1.w;
            float4 t0 = make_float4(f2tf32(bv0.x), f2tf32(bv0.y), f2tf32(bv0.z), f2tf32(bv0.w));
            float4 t1 = make_float4(f2tf32(bv1.x), f2tf32(bv1.y), f2tf32(bv1.z), f2tf32(bv1.w));
            *(float4*)&Bs[n][br][bc]     = t0;
            *(float4*)&Bs[n][br][bc + 4] = t1;
        }
    }

    // epilogue: c0,c1 = (row g, cols 2tg,2tg+1); c2,c3 = (row g+8)
    #pragma unroll
    for (int mt = 0; mt < 2; mt++) {
        const long r0 = m0 + wm + mt * 16 + g;
        #pragma unroll
        for (int nt = 0; nt < 8; nt++) {
            const long col = n0 + wn + nt * 8 + 2 * tg;
            *(float2*)&Cb[r0 * S_ + col]       = make_float2(acc[mt][nt][0], acc[mt][nt][1]);
            *(float2*)&Cb[(r0 + 8) * S_ + col] = make_float2(acc[mt][nt][2], acc[mt][nt][3]);
        }
    }
}

// ---------------------------------------------------------------------------
// fp32 SGEMM (kept for the small q / output projections).
//   C[M,N] = A[M,K] * B^T, B row-major [N,K].
// ---------------------------------------------------------------------------
__global__ __launch_bounds__(256, 2)
void sgemm_nt(const float* __restrict__ A, const float* __restrict__ B,
              float* __restrict__ C, int M, int N, int K)
{
    __shared__ float As[8][132];
    __shared__ float Bs[8][132];

    const int tid  = threadIdx.x;
    const int tx   = tid & 15;
    const int ty   = tid >> 4;
    const int m0   = blockIdx.y * 128;
    const int n0   = blockIdx.x * 128;
    const int lrow = tid >> 1;
    const int lcol = (tid & 1) * 4;

    float acc[2][2][4][4];
    #pragma unroll
    for (int qm = 0; qm < 2; qm++)
        #pragma unroll
        for (int qn = 0; qn < 2; qn++)
            #pragma unroll
            for (int i = 0; i < 4; i++)
                #pragma unroll
                for (int j = 0; j < 4; j++)
                    acc[qm][qn][i][j] = 0.f;

    const int kIter = K >> 3;
    float4 av = *(const float4*)&A[(long)(m0 + lrow) * K + lcol];
    float4 bv = *(const float4*)&B[(long)(n0 + lrow) * K + lcol];

    for (int it = 0; it < kIter; ++it) {
        __syncthreads();
        As[lcol + 0][lrow] = av.x; As[lcol + 1][lrow] = av.y;
        As[lcol + 2][lrow] = av.z; As[lcol + 3][lrow] = av.w;
        Bs[lcol + 0][lrow] = bv.x; Bs[lcol + 1][lrow] = bv.y;
        Bs[lcol + 2][lrow] = bv.z; Bs[lcol + 3][lrow] = bv.w;
        __syncthreads();

        if (it + 1 < kIter) {
            const int k0 = (it + 1) << 3;
            av = *(const float4*)&A[(long)(m0 + lrow) * K + k0 + lcol];
            bv = *(const float4*)&B[(long)(n0 + lrow) * K + k0 + lcol];
        }

        #pragma unroll
        for (int kk = 0; kk < 8; kk++) {
            float4 a0 = *(const float4*)&As[kk][ty * 4];
            float4 a1 = *(const float4*)&As[kk][64 + ty * 4];
            float4 b0 = *(const float4*)&Bs[kk][tx * 4];
            float4 b1 = *(const float4*)&Bs[kk][64 + tx * 4];
            float ar[2][4] = {{a0.x, a0.y, a0.z, a0.w}, {a1.x, a1.y, a1.z, a1.w}};
            float br[2][4] = {{b0.x, b0.y, b0.z, b0.w}, {b1.x, b1.y, b1.z, b1.w}};
            #pragma unroll
            for (int qm = 0; qm < 2; qm++)
                #pragma unroll
                for (int i = 0; i < 4; i++)
                    #pragma unroll
                    for (int qn = 0; qn < 2; qn++)
                        #pragma unroll
                        for (int j = 0; j < 4; j++)
                            acc[qm][qn][i][j] += ar[qm][i] * br[qn][j];
        }
    }

    #pragma unroll
    for (int qm = 0; qm < 2; qm++)
        #pragma unroll
        for (int i = 0; i < 4; i++) {
            const long row = m0 + qm * 64 + ty * 4 + i;
            #pragma unroll
            for (int qn = 0; qn < 2; qn++) {
                float4 w = make_float4(acc[qm][qn][i][0], acc[qm][qn][i][1],
                                       acc[qm][qn][i][2], acc[qm][qn][i][3]);
                *(float4*)&C[row * N + n0 + qn * 64 + tx * 4] = w;
            }
        }
}

// ---------------------------------------------------------------------------
// Fused attention (unchanged this round): one block per (b, head), online
// softmax over S in tiles of 128. k/v come from the fused g_kv buffer.
// ---------------------------------------------------------------------------
#define ATTN_SMEM ((2 * 64 * 128 + 64 * 65) * 4)

__global__ __launch_bounds__(256, 1)
void attn_kernel(const float* __restrict__ gq, const float* __restrict__ gkv,
                 float* __restrict__ go)
{
    extern __shared__ float sm[];
    float* Ks = sm;
    float* Vs = sm + 64 * 128;
    float* Qs = sm + 2 * 64 * 128;

    const int bh = blockIdx.x;
    const int b  = bh >> 3;
    const int h  = bh & 7;
    const int tid = threadIdx.x;
    const int t  = tid >> 2;
    const int sc = tid & 3;
    const int sb = sc * 32;

    const float* qb = gq + ((long)b * T_) * INNER + h * DIMH;
    for (int i = tid; i < T_ * 16; i += 256) {
        const int r = i >> 4, c = (i & 15) << 2;
        float4 qv = *(const float4*)&qb[(long)r * INNER + c];
        Qs[r * 65 + c + 0] = qv.x * 0.125f;
        Qs[r * 65 + c + 1] = qv.y * 0.125f;
        Qs[r * 65 + c + 2] = qv.z * 0.125f;
        Qs[r * 65 + c + 3] = qv.w * 0.125f;
    }
    __syncthreads();

    float q_r[64];
    #pragma unroll
    for (int d = 0; d < 64; d++) q_r[d] = Qs[t * 65 + d];

    float acc[64];
    #pragma unroll
    for (int d = 0; d < 64; d++) acc[d] = 0.f;
    float m_run = -3.0e38f;
    float l_run = 0.f;

    const float* kb = gkv + ((long)b * 2 * INNER + h * DIMH) * S_;
    const float* vb = gkv + ((long)b * 2 * INNER + INNER + h * DIMH) * S_;

    for (int s0 = 0; s0 < S_; s0 += 128) {
        __syncthreads();
        for (int i = tid; i < 64 * 32; i += 256) {
            const int d = i >> 5, c = (i & 31) << 2;
            *(float4*)&Ks[d * 128 + c] = *(const float4*)&kb[(long)d * S_ + s0 + c];
            *(float4*)&Vs[d * 128 + c] = *(const float4*)&vb[(long)d * S_ + s0 + c];
        }
        __syncthreads();

        float4 scr[8];
        #pragma unroll
        for (int j = 0; j < 8; j++) scr[j] = make_float4(0.f, 0.f, 0.f, 0.f);
        #pragma unroll
        for (int d = 0; d < 64; d++) {
            const float qd = q_r[d];
            const float4* kr = (const float4*)&Ks[d * 128 + sb];
            #pragma unroll
            for (int j = 0; j < 8; j++) {
                float4 k4 = kr[j];
                scr[j].x += qd * k4.x;
                scr[j].y += qd * k4.y;
                scr[j].z += qd * k4.z;
                scr[j].w += qd * k4.w;
            }
        }

        float mt = -3.0e38f;
        #pragma unroll
        for (int j = 0; j < 8; j++)
            mt = fmaxf(mt, fmaxf(fmaxf(scr[j].x, scr[j].y), fmaxf(scr[j].z, scr[j].w)));
        mt = fmaxf(mt, __shfl_xor_sync(0xffffffffu, mt, 1));
        mt = fmaxf(mt, __shfl_xor_sync(0xffffffffu, mt, 2));
        const float m_new = fmaxf(m_run, mt);
        const float corr  = __expf(m_run - m_new);

        float ls = 0.f;
        #pragma unroll
        for (int j = 0; j < 8; j++) {
            scr[j].x = __expf(scr[j].x - m_new);
            scr[j].y = __expf(scr[j].y - m_new);
            scr[j].z = __expf(scr[j].z - m_new);
            scr[j].w = __expf(scr[j].w - m_new);
            ls += scr[j].x + scr[j].y + scr[j].z + scr[j].w;
        }
        ls += __shfl_xor_sync(0xffffffffu, ls, 1);
        ls += __shfl_xor_sync(0xffffffffu, ls, 2);
        l_run = l_run * corr + ls;
        m_run = m_new;

        #pragma unroll
        for (int d = 0; d < 64; d++) acc[d] *= corr;

        #pragma unroll
        for (int d = 0; d < 64; d++) {
            const float4* vr = (const float4*)&Vs[d * 128 + sb];
            float a = acc[d];
            #pragma unroll
            for (int j = 0; j < 8; j++) {
                float4 v4 = vr[j];
                a += scr[j].x * v4.x;
                a += scr[j].y * v4.y;
                a += scr[j].z * v4.z;
                a += scr[j].w * v4.w;
            }
            acc[d] = a;
        }
    }

    const float inv = 1.f / l_run;
    #pragma unroll
    for (int d = 0; d < 64; d++) {
        float a = acc[d];
        a += __shfl_xor_sync(0xffffffffu, a, 1);
        a += __shfl_xor_sync(0xffffffffu, a, 2);
        acc[d] = a * inv;
    }
    if (sc == 0) {
        float* ob = go + ((long)(b * T_ + t)) * INNER + h * DIMH;
        #pragma unroll
        for (int j = 0; j < 16; j++) {
            float4 w = make_float4(acc[4 * j + 0], acc[4 * j + 1],
                                   acc[4 * j + 2], acc[4 * j + 3]);
            *(float4*)&ob[4 * j] = w;
        }
    }
}

// ---------------------------------------------------------------------------
extern "C" void kernel_launch(void* const* d_in, const int* in_sizes, int n_in,
                              void* d_out, int out_size)
{
    const float* vis  = (const float*)d_in[0]; // (B,C,H,W) = (B,C,S)
    const float* lang = (const float*)d_in[1]; // (B,T,C)
    // d_in[2] = mask (unused)
    const float* Wq   = (const float*)d_in[3]; // (inner,C)
    const float* Wk   = (const float*)d_in[4];
    const float* Wv   = (const float*)d_in[5];
    const float* Wo   = (const float*)d_in[6]; // (C,inner)
    float* out = (float*)d_out;

    float *q, *kv, *ao, *wkv;
    cudaGetSymbolAddress((void**)&q,   g_q);
    cudaGetSymbolAddress((void**)&kv,  g_kv);
    cudaGetSymbolAddress((void**)&ao,  g_ao);
    cudaGetSymbolAddress((void**)&wkv, g_wkv);

    cudaFuncSetAttribute(attn_kernel, cudaFuncAttributeMaxDynamicSharedMemorySize,
                         ATTN_SMEM);

    // concat + tf32-round Wk,Wv
    prep_wkv<<<INNER * C_ / 256, 256>>>(Wk, Wv, wkv);

    // q projection (fp32): (1024,512) = lang @ Wq^T
    sgemm_nt<<<dim3(INNER / 128, (B_ * T_) / 128), 256>>>(lang, Wq, q, B_ * T_, INNER, C_);

    // fused k+v projection (tf32 tensor cores): per batch (1024,4096)
    gemm_kv<<<dim3(S_ / GBN, (2 * INNER) / GBM, B_), 256>>>(wkv, vis, kv);

    // fused attention
    attn_kernel<<<B_ * NHEAD, 256, ATTN_SMEM>>>(q, kv, ao);

    // output projection (fp32): (1024,512) = ao @ Wo^T
    sgemm_nt<<<dim3(C_ / 128, (B_ * T_) / 128), 256>>>(ao, Wo, out, B_ * T_, C_, INNER);
}

// round 5
// speedup vs baseline: 1.3364x; 1.0816x over previous
#include <cuda_runtime.h>
#include <cuda_fp16.h>
#include <cstdint>

// Problem constants
#define B_    16
#define T_    64
#define C_    512
#define S_    4096
#define INNER 512
#define DIMH  64
#define NHEAD 8
// SCALE = 0.125

// Scratch (device globals; no allocations allowed)
__device__ float    g_q   [B_ * T_ * INNER];
__device__ float    g_kv  [(long)B_ * 2 * INNER * S_];   // (B, [k;v] 1024, S)
__device__ float    g_ao  [B_ * T_ * INNER];
__device__ __half   g_w16 [2 * INNER * C_];              // concat(Wk,Wv) fp16, row-major [1024][512]
__device__ uint32_t g_v16p[(long)B_ * (C_ / 2) * S_];    // vis fp16 pair-packed [b][c2][s] (c=2*c2 lo, 2*c2+1 hi)

// ---------------------------------------------------------------------------
// prep: weights -> fp16 (RN)
// ---------------------------------------------------------------------------
__global__ void prep_w16(const float* __restrict__ Wk, const float* __restrict__ Wv,
                         __half* __restrict__ w16)
{
    const int i = blockIdx.x * 256 + threadIdx.x;   // 0 .. 262143
    w16[i]              = __float2half_rn(Wk[i]);
    w16[INNER * C_ + i] = __float2half_rn(Wv[i]);
}

// ---------------------------------------------------------------------------
// prep: vis (b,c,s) f32 -> pair-packed fp16 (b, c/2, s) with (c, c+1) in one u32
// ---------------------------------------------------------------------------
__global__ void prep_vis16(const float* __restrict__ vis, uint32_t* __restrict__ vp)
{
    const long i  = (long)blockIdx.x * 256 + threadIdx.x;  // over B*256*4096
    const long s  = i & (S_ - 1);
    const long c2 = (i >> 12) & 255;
    const long b  = i >> 20;
    const float* src = vis + (((b * C_) + 2 * c2) << 12) + s;
    const __half lo = __float2half_rn(src[0]);
    const __half hi = __float2half_rn(src[S_]);
    vp[i] = ((uint32_t)__half_as_ushort(hi) << 16) | (uint32_t)__half_as_ushort(lo);
}

// ---------------------------------------------------------------------------
// Fused k/v projection, fp16 tensor-core GEMM (mma.sync.m16n8k16, f32 accum).
//   C[b][m][n] = sum_k w16[m][k] * vis16[b][k][n]
// Block 128x128, BK=32 (2 K-steps of 16). 256 threads, 8 warps 4(m)x2(n),
// warp tile 32x64. Smem holds fp16 k-PAIRS (u32), [k2][row] stride 136:
// fragment address = (k2)*136 + idx -> bank = 8*tg + idx  (conflict-free).
// ---------------------------------------------------------------------------
__global__ __launch_bounds__(256, 2)
void gemm_kv_f16(const __half* __restrict__ A16,      // [1024][512] halves
                 const uint32_t* __restrict__ Bp,     // [16][256][4096] pairs
                 float* __restrict__ Ckv)             // [16][1024][4096] f32
{
    __shared__ uint32_t As[2][16][136];
    __shared__ uint32_t Bs[2][16][136];

    const int b  = blockIdx.z;
    const int m0 = blockIdx.y * 128;
    const int n0 = blockIdx.x * 128;
    const uint32_t* Ap = (const uint32_t*)A16;              // pair view [1024][256]
    const uint32_t* Bb = Bp + (long)b * (C_ / 2) * S_;
    float*          Cb = Ckv + (long)b * 2 * INNER * S_;

    const int tid  = threadIdx.x;
    const int warp = tid >> 5;
    const int lane = tid & 31;
    const int wm   = (warp >> 1) * 32;
    const int wn   = (warp & 1) * 64;
    const int g    = lane >> 2;
    const int tg   = lane & 3;

    // loaders: A -> row ar, 8 pair-cols from apc; B -> k2 row brb, 8 s from bsc
    const int ar  = tid >> 1;
    const int apc = (tid & 1) * 8;
    const int brb = tid >> 4;
    const int bsc = (tid & 15) * 8;

    float acc[2][8][4];
    #pragma unroll
    for (int mt = 0; mt < 2; mt++)
        #pragma unroll
        for (int nt = 0; nt < 8; nt++)
            #pragma unroll
            for (int i = 0; i < 4; i++)
                acc[mt][nt][i] = 0.f;

    const int nIter = C_ / 32;   // 16

    // prefetch iter 0 (kc2 = 0)
    uint4 av0 = *(const uint4*)&Ap[(long)(m0 + ar) * (C_ / 2) + apc];
    uint4 av1 = *(const uint4*)&Ap[(long)(m0 + ar) * (C_ / 2) + apc + 4];
    uint4 bv0 = *(const uint4*)&Bb[(long)brb * S_ + n0 + bsc];
    uint4 bv1 = *(const uint4*)&Bb[(long)brb * S_ + n0 + bsc + 4];

    for (int it = 0; it < nIter; ++it) {
        const int c = it & 1;
        __syncthreads();   // prior compute on this buffer done
        As[c][apc + 0][ar] = av0.x; As[c][apc + 1][ar] = av0.y;
        As[c][apc + 2][ar] = av0.z; As[c][apc + 3][ar] = av0.w;
        As[c][apc + 4][ar] = av1.x; As[c][apc + 5][ar] = av1.y;
        As[c][apc + 6][ar] = av1.z; As[c][apc + 7][ar] = av1.w;
        *(uint4*)&Bs[c][brb][bsc]     = bv0;
        *(uint4*)&Bs[c][brb][bsc + 4] = bv1;
        __syncthreads();

        if (it + 1 < nIter) {
            const int kc2 = (it + 1) * 16;
            av0 = *(const uint4*)&Ap[(long)(m0 + ar) * (C_ / 2) + kc2 + apc];
            av1 = *(const uint4*)&Ap[(long)(m0 + ar) * (C_ / 2) + kc2 + apc + 4];
            bv0 = *(const uint4*)&Bb[(long)(kc2 + brb) * S_ + n0 + bsc];
            bv1 = *(const uint4*)&Bb[(long)(kc2 + brb) * S_ + n0 + bsc + 4];
        }

        #pragma unroll
        for (int ks = 0; ks < 2; ks++) {
            const int kb = ks * 8;
            uint32_t bf[8][2];
            #pragma unroll
            for (int nt = 0; nt < 8; nt++) {
                bf[nt][0] = Bs[c][kb + tg]    [wn + nt * 8 + g];
                bf[nt][1] = Bs[c][kb + tg + 4][wn + nt * 8 + g];
            }
            #pragma unroll
            for (int mt = 0; mt < 2; mt++) {
                const int mi = wm + mt * 16 + g;
                uint32_t a0 = As[c][kb + tg]    [mi];
                uint32_t a1 = As[c][kb + tg]    [mi + 8];
                uint32_t a2 = As[c][kb + tg + 4][mi];
                uint32_t a3 = As[c][kb + tg + 4][mi + 8];
                #pragma unroll
                for (int nt = 0; nt < 8; nt++) {
                    asm volatile(
                        "mma.sync.aligned.m16n8k16.row.col.f32.f16.f16.f32 "
                        "{%0,%1,%2,%3}, {%4,%5,%6,%7}, {%8,%9}, {%0,%1,%2,%3};"
                        : "+f"(acc[mt][nt][0]), "+f"(acc[mt][nt][1]),
                          "+f"(acc[mt][nt][2]), "+f"(acc[mt][nt][3])
                        : "r"(a0), "r"(a1), "r"(a2), "r"(a3),
                          "r"(bf[nt][0]), "r"(bf[nt][1]));
                }
            }
        }
    }

    // epilogue: c0,c1 = (row g, cols 2tg,2tg+1); c2,c3 = row g+8
    #pragma unroll
    for (int mt = 0; mt < 2; mt++) {
        const long r0 = m0 + wm + mt * 16 + g;
        #pragma unroll
        for (int nt = 0; nt < 8; nt++) {
            const long col = n0 + wn + nt * 8 + 2 * tg;
            *(float2*)&Cb[r0 * S_ + col]       = make_float2(acc[mt][nt][0], acc[mt][nt][1]);
            *(float2*)&Cb[(r0 + 8) * S_ + col] = make_float2(acc[mt][nt][2], acc[mt][nt][3]);
        }
    }
}

// ---------------------------------------------------------------------------
// fp32 SGEMM (small q / output projections).  C[M,N] = A[M,K] * B^T.
// ---------------------------------------------------------------------------
__global__ __launch_bounds__(256, 2)
void sgemm_nt(const float* __restrict__ A, const float* __restrict__ B,
              float* __restrict__ C, int M, int N, int K)
{
    __shared__ float As[8][132];
    __shared__ float Bs[8][132];

    const int tid  = threadIdx.x;
    const int tx   = tid & 15;
    const int ty   = tid >> 4;
    const int m0   = blockIdx.y * 128;
    const int n0   = blockIdx.x * 128;
    const int lrow = tid >> 1;
    const int lcol = (tid & 1) * 4;

    float acc[2][2][4][4];
    #pragma unroll
    for (int qm = 0; qm < 2; qm++)
        #pragma unroll
        for (int qn = 0; qn < 2; qn++)
            #pragma unroll
            for (int i = 0; i < 4; i++)
                #pragma unroll
                for (int j = 0; j < 4; j++)
                    acc[qm][qn][i][j] = 0.f;

    const int kIter = K >> 3;
    float4 av = *(const float4*)&A[(long)(m0 + lrow) * K + lcol];
    float4 bv = *(const float4*)&B[(long)(n0 + lrow) * K + lcol];

    for (int it = 0; it < kIter; ++it) {
        __syncthreads();
        As[lcol + 0][lrow] = av.x; As[lcol + 1][lrow] = av.y;
        As[lcol + 2][lrow] = av.z; As[lcol + 3][lrow] = av.w;
        Bs[lcol + 0][lrow] = bv.x; Bs[lcol + 1][lrow] = bv.y;
        Bs[lcol + 2][lrow] = bv.z; Bs[lcol + 3][lrow] = bv.w;
        __syncthreads();

        if (it + 1 < kIter) {
            const int k0 = (it + 1) << 3;
            av = *(const float4*)&A[(long)(m0 + lrow) * K + k0 + lcol];
            bv = *(const float4*)&B[(long)(n0 + lrow) * K + k0 + lcol];
        }

        #pragma unroll
        for (int kk = 0; kk < 8; kk++) {
            float4 a0 = *(const float4*)&As[kk][ty * 4];
            float4 a1 = *(const float4*)&As[kk][64 + ty * 4];
            float4 b0 = *(const float4*)&Bs[kk][tx * 4];
            float4 b1 = *(const float4*)&Bs[kk][64 + tx * 4];
            float ar[2][4] = {{a0.x, a0.y, a0.z, a0.w}, {a1.x, a1.y, a1.z, a1.w}};
            float br[2][4] = {{b0.x, b0.y, b0.z, b0.w}, {b1.x, b1.y, b1.z, b1.w}};
            #pragma unroll
            for (int qm = 0; qm < 2; qm++)
                #pragma unroll
                for (int i = 0; i < 4; i++)
                    #pragma unroll
                    for (int qn = 0; qn < 2; qn++)
                        #pragma unroll
                        for (int j = 0; j < 4; j++)
                            acc[qm][qn][i][j] += ar[qm][i] * br[qn][j];
        }
    }

    #pragma unroll
    for (int qm = 0; qm < 2; qm++)
        #pragma unroll
        for (int i = 0; i < 4; i++) {
            const long row = m0 + qm * 64 + ty * 4 + i;
            #pragma unroll
            for (int qn = 0; qn < 2; qn++) {
                float4 w = make_float4(acc[qm][qn][i][0], acc[qm][qn][i][1],
                                       acc[qm][qn][i][2], acc[qm][qn][i][3]);
                *(float4*)&C[row * N + n0 + qn * 64 + tx * 4] = w;
            }
        }
}

// ---------------------------------------------------------------------------
// Fused attention (unchanged): one block per (b, head), online softmax.
// ---------------------------------------------------------------------------
#define ATTN_SMEM ((2 * 64 * 128 + 64 * 65) * 4)

__global__ __launch_bounds__(256, 1)
void attn_kernel(const float* __restrict__ gq, const float* __restrict__ gkv,
                 float* __restrict__ go)
{
    extern __shared__ float sm[];
    float* Ks = sm;
    float* Vs = sm + 64 * 128;
    float* Qs = sm + 2 * 64 * 128;

    const int bh = blockIdx.x;
    const int b  = bh >> 3;
    const int h  = bh & 7;
    const int tid = threadIdx.x;
    const int t  = tid >> 2;
    const int sc = tid & 3;
    const int sb = sc * 32;

    const float* qb = gq + ((long)b * T_) * INNER + h * DIMH;
    for (int i = tid; i < T_ * 16; i += 256) {
        const int r = i >> 4, c = (i & 15) << 2;
        float4 qv = *(const float4*)&qb[(long)r * INNER + c];
        Qs[r * 65 + c + 0] = qv.x * 0.125f;
        Qs[r * 65 + c + 1] = qv.y * 0.125f;
        Qs[r * 65 + c + 2] = qv.z * 0.125f;
        Qs[r * 65 + c + 3] = qv.w * 0.125f;
    }
    __syncthreads();

    float q_r[64];
    #pragma unroll
    for (int d = 0; d < 64; d++) q_r[d] = Qs[t * 65 + d];

    float acc[64];
    #pragma unroll
    for (int d = 0; d < 64; d++) acc[d] = 0.f;
    float m_run = -3.0e38f;
    float l_run = 0.f;

    const float* kb = gkv + ((long)b * 2 * INNER + h * DIMH) * S_;
    const float* vb = gkv + ((long)b * 2 * INNER + INNER + h * DIMH) * S_;

    for (int s0 = 0; s0 < S_; s0 += 128) {
        __syncthreads();
        for (int i = tid; i < 64 * 32; i += 256) {
            const int d = i >> 5, c = (i & 31) << 2;
            *(float4*)&Ks[d * 128 + c] = *(const float4*)&kb[(long)d * S_ + s0 + c];
            *(float4*)&Vs[d * 128 + c] = *(const float4*)&vb[(long)d * S_ + s0 + c];
        }
        __syncthreads();

        float4 scr[8];
        #pragma unroll
        for (int j = 0; j < 8; j++) scr[j] = make_float4(0.f, 0.f, 0.f, 0.f);
        #pragma unroll
        for (int d = 0; d < 64; d++) {
            const float qd = q_r[d];
            const float4* kr = (const float4*)&Ks[d * 128 + sb];
            #pragma unroll
            for (int j = 0; j < 8; j++) {
                float4 k4 = kr[j];
                scr[j].x += qd * k4.x;
                scr[j].y += qd * k4.y;
                scr[j].z += qd * k4.z;
                scr[j].w += qd * k4.w;
            }
        }

        float mt = -3.0e38f;
        #pragma unroll
        for (int j = 0; j < 8; j++)
            mt = fmaxf(mt, fmaxf(fmaxf(scr[j].x, scr[j].y), fmaxf(scr[j].z, scr[j].w)));
        mt = fmaxf(mt, __shfl_xor_sync(0xffffffffu, mt, 1));
        mt = fmaxf(mt, __shfl_xor_sync(0xffffffffu, mt, 2));
        const float m_new = fmaxf(m_run, mt);
        const float corr  = __expf(m_run - m_new);

        float ls = 0.f;
        #pragma unroll
        for (int j = 0; j < 8; j++) {
            scr[j].x = __expf(scr[j].x - m_new);
            scr[j].y = __expf(scr[j].y - m_new);
            scr[j].z = __expf(scr[j].z - m_new);
            scr[j].w = __expf(scr[j].w - m_new);
            ls += scr[j].x + scr[j].y + scr[j].z + scr[j].w;
        }
        ls += __shfl_xor_sync(0xffffffffu, ls, 1);
        ls += __shfl_xor_sync(0xffffffffu, ls, 2);
        l_run = l_run * corr + ls;
        m_run = m_new;

        #pragma unroll
        for (int d = 0; d < 64; d++) acc[d] *= corr;

        #pragma unroll
        for (int d = 0; d < 64; d++) {
            const float4* vr = (const float4*)&Vs[d * 128 + sb];
            float a = acc[d];
            #pragma unroll
            for (int j = 0; j < 8; j++) {
                float4 v4 = vr[j];
                a += scr[j].x * v4.x;
                a += scr[j].y * v4.y;
                a += scr[j].z * v4.z;
                a += scr[j].w * v4.w;
            }
            acc[d] = a;
        }
    }

    const float inv = 1.f / l_run;
    #pragma unroll
    for (int d = 0; d < 64; d++) {
        float a = acc[d];
        a += __shfl_xor_sync(0xffffffffu, a, 1);
        a += __shfl_xor_sync(0xffffffffu, a, 2);
        acc[d] = a * inv;
    }
    if (sc == 0) {
        float* ob = go + ((long)(b * T_ + t)) * INNER + h * DIMH;
        #pragma unroll
        for (int j = 0; j < 16; j++) {
            float4 w = make_float4(acc[4 * j + 0], acc[4 * j + 1],
                                   acc[4 * j + 2], acc[4 * j + 3]);
            *(float4*)&ob[4 * j] = w;
        }
    }
}

// ---------------------------------------------------------------------------
extern "C" void kernel_launch(void* const* d_in, const int* in_sizes, int n_in,
                              void* d_out, int out_size)
{
    const float* vis  = (const float*)d_in[0]; // (B,C,H,W) = (B,C,S)
    const float* lang = (const float*)d_in[1]; // (B,T,C)
    // d_in[2] = mask (unused)
    const float* Wq   = (const float*)d_in[3];
    const float* Wk   = (const float*)d_in[4];
    const float* Wv   = (const float*)d_in[5];
    const float* Wo   = (const float*)d_in[6];
    float* out = (float*)d_out;

    float *q, *kv, *ao;
    __half* w16;
    uint32_t* v16p;
    cudaGetSymbolAddress((void**)&q,    g_q);
    cudaGetSymbolAddress((void**)&kv,   g_kv);
    cudaGetSymbolAddress((void**)&ao,   g_ao);
    cudaGetSymbolAddress((void**)&w16,  g_w16);
    cudaGetSymbolAddress((void**)&v16p, g_v16p);

    cudaFuncSetAttribute(attn_kernel, cudaFuncAttributeMaxDynamicSharedMemorySize,
                         ATTN_SMEM);

    // fp16 prep (RN conversions)
    prep_w16<<<INNER * C_ / 256, 256>>>(Wk, Wv, w16);
    prep_vis16<<<(int)(((long)B_ * (C_ / 2) * S_) / 256), 256>>>(vis, v16p);

    // q projection (fp32 SIMT): (1024,512) = lang @ Wq^T
    sgemm_nt<<<dim3(INNER / 128, (B_ * T_) / 128), 256>>>(lang, Wq, q, B_ * T_, INNER, C_);

    // fused k+v projection, fp16 tensor cores
    gemm_kv_f16<<<dim3(S_ / 128, (2 * INNER) / 128, B_), 256>>>(w16, v16p, kv);

    // fused attention
    attn_kernel<<<B_ * NHEAD, 256, ATTN_SMEM>>>(q, kv, ao);

    // output projection (fp32 SIMT): (1024,512) = ao @ Wo^T
    sgemm_nt<<<dim3(C_ / 128, (B_ * T_) / 128), 256>>>(ao, Wo, out, B_ * T_, C_, INNER);
}

// round 7
// speedup vs baseline: 6.2625x; 4.6860x over previous
#include <cuda_runtime.h>
#include <cuda_fp16.h>
#include <cstdint>

// Problem constants
#define B_    16
#define T_    64
#define C_    512
#define S_    4096
#define INNER 512
#define DIMH  64
#define NHEAD 8
#define BH_   (B_ * NHEAD)
#define SPLIT 4
#define S_PER (S_ / SPLIT)      // 1024
// SCALE = 0.125 (folded into q16)

// Scratch (device globals; no allocations allowed)
__device__ float    g_q   [B_ * T_ * INNER];             // q projection f32 (B,T,inner)
__device__ float    g_ao  [B_ * T_ * INNER];             // attention out (B,T,inner)
__device__ __half   g_w16 [2 * INNER * C_];              // concat(Wk,Wv) fp16
__device__ uint32_t g_v16p[(long)B_ * (C_ / 2) * S_];    // vis fp16 pair-packed
__device__ __half   g_q16 [BH_ * T_ * DIMH];             // q fp16, (bh,t,d), pre-scaled
__device__ __half   g_k16 [(long)BH_ * S_ * DIMH];       // K fp16 s-major (bh,s,d)
__device__ __half   g_v16 [(long)BH_ * DIMH * S_];       // V fp16 d-major (bh,d,s)
__device__ float    g_op  [(long)SPLIT * BH_ * T_ * DIMH]; // partial O
__device__ float    g_ml  [SPLIT * BH_ * T_ * 2];        // partial (m,l)

// pack two fp32 -> one .f16x2 register (lo = first arg)
__device__ __forceinline__ uint32_t f2h2(float lo, float hi) {
    uint32_t r;
    asm("cvt.rn.f16x2.f32 %0, %1, %2;" : "=r"(r) : "f"(hi), "f"(lo));
    return r;
}

// ---------------------------------------------------------------------------
__global__ void prep_w16(const float* __restrict__ Wk, const float* __restrict__ Wv,
                         __half* __restrict__ w16)
{
    const int i = blockIdx.x * 256 + threadIdx.x;
    w16[i]              = __float2half_rn(Wk[i]);
    w16[INNER * C_ + i] = __float2half_rn(Wv[i]);
}

__global__ void prep_vis16(const float* __restrict__ vis, uint32_t* __restrict__ vp)
{
    const long i  = (long)blockIdx.x * 256 + threadIdx.x;
    const long s  = i & (S_ - 1);
    const long c2 = (i >> 12) & 255;
    const long b  = i >> 20;
    const float* src = vis + (((b * C_) + 2 * c2) << 12) + s;
    vp[i] = f2h2(src[0], src[S_]);
}

// q f32 (B,T,inner) -> q16 (bh,t,d), scaled by 0.125
__global__ void prep_q16(const float* __restrict__ q, __half* __restrict__ q16)
{
    const int i = blockIdx.x * 256 + threadIdx.x;   // 0 .. 524287
    const int d = i & 63;
    const int h = (i >> 6) & 7;
    const int t = (i >> 9) & 63;
    const int b = i >> 15;
    q16[(((b * 8 + h) * T_) + t) * DIMH + d] = __float2half_rn(q[i] * 0.125f);
}

// ---------------------------------------------------------------------------
// Fused k/v projection, fp16 mma, epilogue writes fp16 K (s-major) / V (d-major).
// ---------------------------------------------------------------------------
__global__ __launch_bounds__(256, 2)
void gemm_kv_f16(const __half* __restrict__ A16,      // [1024][512]
                 const uint32_t* __restrict__ Bp,     // [16][256][4096] pairs
                 __half* __restrict__ gk,             // (bh,s,d)
                 __half* __restrict__ gv)             // (bh,d,s)
{
    __shared__ uint32_t As[2][16][136];
    __shared__ uint32_t Bs[2][16][136];

    const int b  = blockIdx.z;
    const int m0 = blockIdx.y * 128;
    const int n0 = blockIdx.x * 128;
    const uint32_t* Ap = (const uint32_t*)A16;
    const uint32_t* Bb = Bp + (long)b * (C_ / 2) * S_;

    const int tid  = threadIdx.x;
    const int warp = tid >> 5;
    const int lane = tid & 31;
    const int wm   = (warp >> 1) * 32;
    const int wn   = (warp & 1) * 64;
    const int g    = lane >> 2;
    const int tg   = lane & 3;

    const int ar  = tid >> 1;
    const int apc = (tid & 1) * 8;
    const int brb = tid >> 4;
    const int bsc = (tid & 15) * 8;

    float acc[2][8][4];
    #pragma unroll
    for (int mt = 0; mt < 2; mt++)
        #pragma unroll
        for (int nt = 0; nt < 8; nt++)
            #pragma unroll
            for (int i = 0; i < 4; i++)
                acc[mt][nt][i] = 0.f;

    const int nIter = C_ / 32;

    uint4 av0 = *(const uint4*)&Ap[(long)(m0 + ar) * (C_ / 2) + apc];
    uint4 av1 = *(const uint4*)&Ap[(long)(m0 + ar) * (C_ / 2) + apc + 4];
    uint4 bv0 = *(const uint4*)&Bb[(long)brb * S_ + n0 + bsc];
    uint4 bv1 = *(const uint4*)&Bb[(long)brb * S_ + n0 + bsc + 4];

    for (int it = 0; it < nIter; ++it) {
        const int c = it & 1;
        __syncthreads();
        As[c][apc + 0][ar] = av0.x; As[c][apc + 1][ar] = av0.y;
        As[c][apc + 2][ar] = av0.z; As[c][apc + 3][ar] = av0.w;
        As[c][apc + 4][ar] = av1.x; As[c][apc + 5][ar] = av1.y;
        As[c][apc + 6][ar] = av1.z; As[c][apc + 7][ar] = av1.w;
        *(uint4*)&Bs[c][brb][bsc]     = bv0;
        *(uint4*)&Bs[c][brb][bsc + 4] = bv1;
        __syncthreads();

        if (it + 1 < nIter) {
            const int kc2 = (it + 1) * 16;
            av0 = *(const uint4*)&Ap[(long)(m0 + ar) * (C_ / 2) + kc2 + apc];
            av1 = *(const uint4*)&Ap[(long)(m0 + ar) * (C_ / 2) + kc2 + apc + 4];
            bv0 = *(const uint4*)&Bb[(long)(kc2 + brb) * S_ + n0 + bsc];
            bv1 = *(const uint4*)&Bb[(long)(kc2 + brb) * S_ + n0 + bsc + 4];
        }

        #pragma unroll
        for (int ks = 0; ks < 2; ks++) {
            const int kb = ks * 8;
            uint32_t bf[8][2];
            #pragma unroll
            for (int nt = 0; nt < 8; nt++) {
                bf[nt][0] = Bs[c][kb + tg]    [wn + nt * 8 + g];
                bf[nt][1] = Bs[c][kb + tg + 4][wn + nt * 8 + g];
            }
            #pragma unroll
            for (int mt = 0; mt < 2; mt++) {
                const int mi = wm + mt * 16 + g;
                uint32_t a0 = As[c][kb + tg]    [mi];
                uint32_t a1 = As[c][kb + tg]    [mi + 8];
                uint32_t a2 = As[c][kb + tg + 4][mi];
                uint32_t a3 = As[c][kb + tg + 4][mi + 8];
                #pragma unroll
                for (int nt = 0; nt < 8; nt++) {
                    asm volatile(
                        "mma.sync.aligned.m16n8k16.row.col.f32.f16.f16.f32 "
                        "{%0,%1,%2,%3}, {%4,%5,%6,%7}, {%8,%9}, {%0,%1,%2,%3};"
                        : "+f"(acc[mt][nt][0]), "+f"(acc[mt][nt][1]),
                          "+f"(acc[mt][nt][2]), "+f"(acc[mt][nt][3])
                        : "r"(a0), "r"(a1), "r"(a2), "r"(a3),
                          "r"(bf[nt][0]), "r"(bf[nt][1]));
                }
            }
        }
    }

    // epilogue: K rows (m<512) -> (bh,s,d) scalar halves; V rows -> (bh,d,s) half2
    #pragma unroll
    for (int mt = 0; mt < 2; mt++) {
        const int mA = m0 + wm + mt * 16 + g;
        const int mB = mA + 8;
        #pragma unroll
        for (int nt = 0; nt < 8; nt++) {
            const int col = n0 + wn + nt * 8 + 2 * tg;
            if (m0 < 512) {
                const int hA = mA >> 6, dA = mA & 63;
                const int hB = mB >> 6, dB = mB & 63;
                __half* pA = gk + ((long)(b * 8 + hA) * S_ + col) * DIMH + dA;
                __half* pB = gk + ((long)(b * 8 + hB) * S_ + col) * DIMH + dB;
                pA[0]    = __float2half_rn(acc[mt][nt][0]);
                pA[DIMH] = __float2half_rn(acc[mt][nt][1]);
                pB[0]    = __float2half_rn(acc[mt][nt][2]);
                pB[DIMH] = __float2half_rn(acc[mt][nt][3]);
            } else {
                const int m2A = mA - 512, m2B = mB - 512;
                const int hA = m2A >> 6, dA = m2A & 63;
                const int hB = m2B >> 6, dB = m2B & 63;
                *(uint32_t*)(gv + ((long)(b * 8 + hA) * DIMH + dA) * S_ + col) =
                    f2h2(acc[mt][nt][0], acc[mt][nt][1]);
                *(uint32_t*)(gv + ((long)(b * 8 + hB) * DIMH + dB) * S_ + col) =
                    f2h2(acc[mt][nt][2], acc[mt][nt][3]);
            }
        }
    }
}

// ---------------------------------------------------------------------------
// fp32 SGEMM (q / output projections).  C[M,N] = A[M,K] * B^T.
// ---------------------------------------------------------------------------
__global__ __launch_bounds__(256, 2)
void sgemm_nt(const float* __restrict__ A, const float* __restrict__ B,
              float* __restrict__ C, int M, int N, int K)
{
    __shared__ float As[8][132];
    __shared__ float Bs[8][132];

    const int tid  = threadIdx.x;
    const int tx   = tid & 15;
    const int ty   = tid >> 4;
    const int m0   = blockIdx.y * 128;
    const int n0   = blockIdx.x * 128;
    const int lrow = tid >> 1;
    const int lcol = (tid & 1) * 4;

    float acc[2][2][4][4];
    #pragma unroll
    for (int qm = 0; qm < 2; qm++)
        #pragma unroll
        for (int qn = 0; qn < 2; qn++)
            #pragma unroll
            for (int i = 0; i < 4; i++)
                #pragma unroll
                for (int j = 0; j < 4; j++)
                    acc[qm][qn][i][j] = 0.f;

    const int kIter = K >> 3;
    float4 av = *(const float4*)&A[(long)(m0 + lrow) * K + lcol];
    float4 bv = *(const float4*)&B[(long)(n0 + lrow) * K + lcol];

    for (int it = 0; it < kIter; ++it) {
        __syncthreads();
        As[lcol + 0][lrow] = av.x; As[lcol + 1][lrow] = av.y;
        As[lcol + 2][lrow] = av.z; As[lcol + 3][lrow] = av.w;
        Bs[lcol + 0][lrow] = bv.x; Bs[lcol + 1][lrow] = bv.y;
        Bs[lcol + 2][lrow] = bv.z; Bs[lcol + 3][lrow] = bv.w;
        __syncthreads();

        if (it + 1 < kIter) {
            const int k0 = (it + 1) << 3;
            av = *(const float4*)&A[(long)(m0 + lrow) * K + k0 + lcol];
            bv = *(const float4*)&B[(long)(n0 + lrow) * K + k0 + lcol];
        }

        #pragma unroll
        for (int kk = 0; kk < 8; kk++) {
            float4 a0 = *(const float4*)&As[kk][ty * 4];
            float4 a1 = *(const float4*)&As[kk][64 + ty * 4];
            float4 b0 = *(const float4*)&Bs[kk][tx * 4];
            float4 b1 = *(const float4*)&Bs[kk][64 + tx * 4];
            float ar[2][4] = {{a0.x, a0.y, a0.z, a0.w}, {a1.x, a1.y, a1.z, a1.w}};
            float br[2][4] = {{b0.x, b0.y, b0.z, b0.w}, {b1.x, b1.y, b1.z, b1.w}};
            #pragma unroll
            for (int qm = 0; qm < 2; qm++)
                #pragma unroll
                for (int i = 0; i < 4; i++)
                    #pragma unroll
                    for (int qn = 0; qn < 2; qn++)
                        #pragma unroll
                        for (int j = 0; j < 4; j++)
                            acc[qm][qn][i][j] += ar[qm][i] * br[qn][j];
        }
    }

    #pragma unroll
    for (int qm = 0; qm < 2; qm++)
        #pragma unroll
        for (int i = 0; i < 4; i++) {
            const long row = m0 + qm * 64 + ty * 4 + i;
            #pragma unroll
            for (int qn = 0; qn < 2; qn++) {
                float4 w = make_float4(acc[qm][qn][i][0], acc[qm][qn][i][1],
                                       acc[qm][qn][i][2], acc[qm][qn][i][3]);
                *(float4*)&C[row * N + n0 + qn * 64 + tx * 4] = w;
            }
        }
}

// ---------------------------------------------------------------------------
// Tensor-core flash attention, split-KV.
// Block = (split, bh), 128 threads = 4 warps x m16 rows. S tiles of 128.
// Smem strides padded so all fragment LDS.32 hit banks 4g+tg (conflict-free).
// ---------------------------------------------------------------------------
#define KS_STRIDE 72     // halves per K/Q smem row
#define VS_STRIDE 136    // halves per V smem row

__global__ __launch_bounds__(128)
void attn_f16(const __half* __restrict__ q16, const __half* __restrict__ k16,
              const __half* __restrict__ v16, float* __restrict__ opart,
              float* __restrict__ ml)
{
    __shared__ __half Qs[T_ * KS_STRIDE];       // 64 x 72
    __shared__ __half Ks[128 * KS_STRIDE];      // 128 x 72
    __shared__ __half Vs[DIMH * VS_STRIDE];     // 64 x 136

    const int sp  = blockIdx.x;
    const int bh  = blockIdx.y;
    const int tid = threadIdx.x;
    const int warp = tid >> 5;
    const int lane = tid & 31;
    const int g   = lane >> 2;
    const int tg  = lane & 3;
    const int wm  = warp * 16;

    // stage Q (64 x 64 halves)
    const __half* qb = q16 + (long)bh * T_ * DIMH;
    #pragma unroll
    for (int t = 0; t < 4; t++) {
        const int idx = tid + t * 128;
        const int r = idx >> 3, c8 = idx & 7;
        *(uint4*)&Qs[r * KS_STRIDE + c8 * 8] = *(const uint4*)&qb[r * DIMH + c8 * 8];
    }
    __syncthreads();

    // Q fragments: 4 k-steps over d
    uint32_t aq[4][4];
    #pragma unroll
    for (int ks = 0; ks < 4; ks++) {
        aq[ks][0] = *(const uint32_t*)&Qs[(wm + g)     * KS_STRIDE + ks * 16 + 2 * tg];
        aq[ks][1] = *(const uint32_t*)&Qs[(wm + g + 8) * KS_STRIDE + ks * 16 + 2 * tg];
        aq[ks][2] = *(const uint32_t*)&Qs[(wm + g)     * KS_STRIDE + ks * 16 + 2 * tg + 8];
        aq[ks][3] = *(const uint32_t*)&Qs[(wm + g + 8) * KS_STRIDE + ks * 16 + 2 * tg + 8];
    }

    float accO[8][4];
    #pragma unroll
    for (int nt = 0; nt < 8; nt++)
        #pragma unroll
        for (int i = 0; i < 4; i++) accO[nt][i] = 0.f;
    float m0r = -1e30f, m1r = -1e30f, l0 = 0.f, l1 = 0.f;

    const __half* kb = k16 + ((long)bh * S_ + sp * S_PER) * DIMH;
    const __half* vb = v16 + (long)bh * DIMH * S_ + sp * S_PER;

    for (int tile = 0; tile < S_PER / 128; tile++) {
        __syncthreads();
        #pragma unroll
        for (int t = 0; t < 8; t++) {            // K: 128 x 64 halves
            const int idx = tid + t * 128;
            const int r = idx >> 3, c8 = idx & 7;
            *(uint4*)&Ks[r * KS_STRIDE + c8 * 8] =
                *(const uint4*)&kb[(long)(tile * 128 + r) * DIMH + c8 * 8];
        }
        #pragma unroll
        for (int t = 0; t < 8; t++) {            // V: 64 x 128 halves
            const int idx = tid + t * 128;
            const int r = idx >> 4, c16 = idx & 15;
            *(uint4*)&Vs[r * VS_STRIDE + c16 * 8] =
                *(const uint4*)&vb[(long)r * S_ + tile * 128 + c16 * 8];
        }
        __syncthreads();

        // QK^T: scores 16 rows x 128 cols per warp
        float accS[16][4];
        #pragma unroll
        for (int nt = 0; nt < 16; nt++)
            #pragma unroll
            for (int i = 0; i < 4; i++) accS[nt][i] = 0.f;

        #pragma unroll
        for (int ks = 0; ks < 4; ks++) {
            #pragma unroll
            for (int nt = 0; nt < 16; nt++) {
                uint32_t b0 = *(const uint32_t*)&Ks[(nt * 8 + g) * KS_STRIDE + ks * 16 + 2 * tg];
                uint32_t b1 = *(const uint32_t*)&Ks[(nt * 8 + g) * KS_STRIDE + ks * 16 + 2 * tg + 8];
                asm volatile(
                    "mma.sync.aligned.m16n8k16.row.col.f32.f16.f16.f32 "
                    "{%0,%1,%2,%3}, {%4,%5,%6,%7}, {%8,%9}, {%0,%1,%2,%3};"
                    : "+f"(accS[nt][0]), "+f"(accS[nt][1]),
                      "+f"(accS[nt][2]), "+f"(accS[nt][3])
                    : "r"(aq[ks][0]), "r"(aq[ks][1]), "r"(aq[ks][2]), "r"(aq[ks][3]),
                      "r"(b0), "r"(b1));
            }
        }

        // online softmax (rows g and g+8)
        float mx0 = -1e30f, mx1 = -1e30f;
        #pragma unroll
        for (int nt = 0; nt < 16; nt++) {
            mx0 = fmaxf(mx0, fmaxf(accS[nt][0], accS[nt][1]));
            mx1 = fmaxf(mx1, fmaxf(accS[nt][2], accS[nt][3]));
        }
        mx0 = fmaxf(mx0, __shfl_xor_sync(0xffffffffu, mx0, 1));
        mx0 = fmaxf(mx0, __shfl_xor_sync(0xffffffffu, mx0, 2));
        mx1 = fmaxf(mx1, __shfl_xor_sync(0xffffffffu, mx1, 1));
        mx1 = fmaxf(mx1, __shfl_xor_sync(0xffffffffu, mx1, 2));

        const float mn0 = fmaxf(m0r, mx0);
        const float mn1 = fmaxf(m1r, mx1);
        const float cr0 = __expf(m0r - mn0);
        const float cr1 = __expf(m1r - mn1);
        m0r = mn0; m1r = mn1;

        float s0 = 0.f, s1 = 0.f;
        #pragma unroll
        for (int nt = 0; nt < 16; nt++) {
            accS[nt][0] = __expf(accS[nt][0] - mn0);
            accS[nt][1] = __expf(accS[nt][1] - mn0);
            accS[nt][2] = __expf(accS[nt][2] - mn1);
            accS[nt][3] = __expf(accS[nt][3] - mn1);
            s0 += accS[nt][0] + accS[nt][1];
            s1 += accS[nt][2] + accS[nt][3];
        }
        s0 += __shfl_xor_sync(0xffffffffu, s0, 1);
        s0 += __shfl_xor_sync(0xffffffffu, s0, 2);
        s1 += __shfl_xor_sync(0xffffffffu, s1, 1);
        s1 += __shfl_xor_sync(0xffffffffu, s1, 2);
        l0 = l0 * cr0 + s0;
        l1 = l1 * cr1 + s1;

        #pragma unroll
        for (int nt = 0; nt < 8; nt++) {
            accO[nt][0] *= cr0; accO[nt][1] *= cr0;
            accO[nt][2] *= cr1; accO[nt][3] *= cr1;
        }

        // P -> half2 A-fragments (k = s, 8 k-steps)
        uint32_t ap[8][4];
        #pragma unroll
        for (int ks = 0; ks < 8; ks++) {
            ap[ks][0] = f2h2(accS[2*ks][0],   accS[2*ks][1]);
            ap[ks][1] = f2h2(accS[2*ks][2],   accS[2*ks][3]);
            ap[ks][2] = f2h2(accS[2*ks+1][0], accS[2*ks+1][1]);
            ap[ks][3] = f2h2(accS[2*ks+1][2], accS[2*ks+1][3]);
        }

        // P @ V
        #pragma unroll
        for (int ks = 0; ks < 8; ks++) {
            #pragma unroll
            for (int nt = 0; nt < 8; nt++) {
                uint32_t b0 = *(const uint32_t*)&Vs[(nt * 8 + g) * VS_STRIDE + ks * 16 + 2 * tg];
                uint32_t b1 = *(const uint32_t*)&Vs[(nt * 8 + g) * VS_STRIDE + ks * 16 + 2 * tg + 8];
                asm volatile(
                    "mma.sync.aligned.m16n8k16.row.col.f32.f16.f16.f32 "
                    "{%0,%1,%2,%3}, {%4,%5,%6,%7}, {%8,%9}, {%0,%1,%2,%3};"
                    : "+f"(accO[nt][0]), "+f"(accO[nt][1]),
                      "+f"(accO[nt][2]), "+f"(accO[nt][3])
                    : "r"(ap[ks][0]), "r"(ap[ks][1]), "r"(ap[ks][2]), "r"(ap[ks][3]),
                      "r"(b0), "r"(b1));
            }
        }
    }

    // write partials (unnormalized) + (m, l)
    float* op = opart + ((long)(sp * BH_ + bh) * T_) * DIMH;
    const int rA = wm + g, rB = wm + g + 8;
    #pragma unroll
    for (int nt = 0; nt < 8; nt++) {
        const int col = nt * 8 + 2 * tg;
        *(float2*)&op[rA * DIMH + col] = make_float2(accO[nt][0], accO[nt][1]);
        *(float2*)&op[rB * DIMH + col] = make_float2(accO[nt][2], accO[nt][3]);
    }
    if (tg == 0) {
        float* mlp = ml + ((long)(sp * BH_ + bh) * T_) * 2;
        mlp[rA * 2] = m0r; mlp[rA * 2 + 1] = l0;
        mlp[rB * 2] = m1r; mlp[rB * 2 + 1] = l1;
    }
}

// ---------------------------------------------------------------------------
// split-KV combine -> g_ao (B,T,inner)
// ---------------------------------------------------------------------------
__global__ void attn_combine(const float* __restrict__ opart,
                             const float* __restrict__ ml, float* __restrict__ ao)
{
    const int bh  = blockIdx.x;
    const int b   = bh >> 3;
    const int h   = bh & 7;
    const int tid = threadIdx.x;       // 128
    const int t   = tid >> 1;
    const int d0  = (tid & 1) * 32;

    float m[SPLIT], l[SPLIT];
    float M = -1e30f;
    #pragma unroll
    for (int i = 0; i < SPLIT; i++) {
        m[i] = ml[((long)(i * BH_ + bh) * T_ + t) * 2];
        l[i] = ml[((long)(i * BH_ + bh) * T_ + t) * 2 + 1];
        M = fmaxf(M, m[i]);
    }
    float w[SPLIT], L = 0.f;
    #pragma unroll
    for (int i = 0; i < SPLIT; i++) {
        w[i] = __expf(m[i] - M);
        L += w[i] * l[i];
    }
    const float inv = 1.f / L;

    float* dst = ao + ((long)(b * T_ + t)) * INNER + h * DIMH + d0;
    #pragma unroll
    for (int d = 0; d < 32; d++) {
        float o = 0.f;
        #pragma unroll
        for (int i = 0; i < SPLIT; i++)
            o += w[i] * opart[((long)(i * BH_ + bh) * T_ + t) * DIMH + d0 + d];
        dst[d] = o * inv;
    }
}

// ---------------------------------------------------------------------------
extern "C" void kernel_launch(void* const* d_in, const int* in_sizes, int n_in,
                              void* d_out, int out_size)
{
    const float* vis  = (const float*)d_in[0];
    const float* lang = (const float*)d_in[1];
    // d_in[2] = mask (unused)
    const float* Wq   = (const float*)d_in[3];
    const float* Wk   = (const float*)d_in[4];
    const float* Wv   = (const float*)d_in[5];
    const float* Wo   = (const float*)d_in[6];
    float* out = (float*)d_out;

    float *q, *ao, *op, *ml;
    __half *w16, *q16, *k16, *v16;
    uint32_t* v16p;
    cudaGetSymbolAddress((void**)&q,    g_q);
    cudaGetSymbolAddress((void**)&ao,   g_ao);
    cudaGetSymbolAddress((void**)&w16,  g_w16);
    cudaGetSymbolAddress((void**)&v16p, g_v16p);
    cudaGetSymbolAddress((void**)&q16,  g_q16);
    cudaGetSymbolAddress((void**)&k16,  g_k16);
    cudaGetSymbolAddress((void**)&v16,  g_v16);
    cudaGetSymbolAddress((void**)&op,   g_op);
    cudaGetSymbolAddress((void**)&ml,   g_ml);

    // prep
    prep_w16<<<INNER * C_ / 256, 256>>>(Wk, Wv, w16);
    prep_vis16<<<(int)(((long)B_ * (C_ / 2) * S_) / 256), 256>>>(vis, v16p);

    // q projection (fp32 SIMT) then fp16 repack
    sgemm_nt<<<dim3(INNER / 128, (B_ * T_) / 128), 256>>>(lang, Wq, q, B_ * T_, INNER, C_);
    prep_q16<<<B_ * T_ * INNER / 256, 256>>>(q, q16);

    // fused k+v projection (fp16 tensor cores, fp16 K/V outputs)
    gemm_kv_f16<<<dim3(S_ / 128, (2 * INNER) / 128, B_), 256>>>(w16, v16p, k16, v16);

    // flash attention (tensor cores, split-KV) + combine
    attn_f16<<<dim3(SPLIT, BH_), 128>>>(q16, k16, v16, op, ml);
    attn_combine<<<BH_, 128>>>(op, ml, ao);

    // output projection (fp32 SIMT)
    sgemm_nt<<<dim3(C_ / 128, (B_ * T_) / 128), 256>>>(ao, Wo, out, B_ * T_, C_, INNER);
}

// round 8
// speedup vs baseline: 7.2748x; 1.1616x over previous
#include <cuda_runtime.h>
#include <cuda_fp16.h>
#include <cstdint>

// Problem constants
#define B_    16
#define T_    64
#define C_    512
#define S_    4096
#define INNER 512
#define DIMH  64
#define NHEAD 8
#define BH_   (B_ * NHEAD)
#define SPLIT 4
#define S_PER (S_ / SPLIT)      // 1024
// SCALE = 0.125 (folded into q16)

// Scratch (device globals; no allocations allowed)
__device__ float    g_q   [B_ * T_ * INNER];             // q projection f32 (B,T,inner)
__device__ float    g_ao  [B_ * T_ * INNER];             // attention out (B,T,inner)
__device__ __half   g_w16 [2 * INNER * C_];              // concat(Wk,Wv) fp16
__device__ uint32_t g_v16p[(long)B_ * (C_ / 2) * S_];    // vis fp16 pair-packed
__device__ __half   g_q16 [BH_ * T_ * DIMH];             // q fp16, (bh,t,d), pre-scaled
__device__ __half   g_k16 [(long)BH_ * S_ * DIMH];       // K fp16 s-major (bh,s,d)
__device__ __half   g_v16 [(long)BH_ * DIMH * S_];       // V fp16 d-major (bh,d,s)
__device__ float    g_op  [(long)SPLIT * BH_ * T_ * DIMH]; // partial O
__device__ float    g_ml  [SPLIT * BH_ * T_ * 2];        // partial (m,l)

// pack two fp32 -> one .f16x2 register (lo = first arg)
__device__ __forceinline__ uint32_t f2h2(float lo, float hi) {
    uint32_t r;
    asm("cvt.rn.f16x2.f32 %0, %1, %2;" : "=r"(r) : "f"(hi), "f"(lo));
    return r;
}

__device__ __forceinline__ uint32_t smem_u32(const void* p) {
    uint32_t a;
    asm("{ .reg .u64 t; cvta.to.shared.u64 t, %1; cvt.u32.u64 %0, t; }" : "=r"(a) : "l"(p));
    return a;
}

// ---------------------------------------------------------------------------
__global__ void prep_w16(const float* __restrict__ Wk, const float* __restrict__ Wv,
                         __half* __restrict__ w16)
{
    const int i = blockIdx.x * 256 + threadIdx.x;
    w16[i]              = __float2half_rn(Wk[i]);
    w16[INNER * C_ + i] = __float2half_rn(Wv[i]);
}

__global__ void prep_vis16(const float* __restrict__ vis, uint32_t* __restrict__ vp)
{
    const long i  = (long)blockIdx.x * 256 + threadIdx.x;
    const long s  = i & (S_ - 1);
    const long c2 = (i >> 12) & 255;
    const long b  = i >> 20;
    const float* src = vis + (((b * C_) + 2 * c2) << 12) + s;
    vp[i] = f2h2(src[0], src[S_]);
}

// q f32 (B,T,inner) -> q16 (bh,t,d), scaled by 0.125
__global__ void prep_q16(const float* __restrict__ q, __half* __restrict__ q16)
{
    const int i = blockIdx.x * 256 + threadIdx.x;   // 0 .. 524287
    const int d = i & 63;
    const int h = (i >> 6) & 7;
    const int t = (i >> 9) & 63;
    const int b = i >> 15;
    q16[(((b * 8 + h) * T_) + t) * DIMH + d] = __float2half_rn(q[i] * 0.125f);
}

// ---------------------------------------------------------------------------
// Fused k/v projection, fp16 mma, 4-stage cp.async pipeline.
//   C[b][m][n] = sum_k w16[m][k] * vis16[b][k][n]
// A smem row-major [m][k2] pad 20 (fragment banks (20g+tg)%32 all distinct);
// B smem [k2][s] stride 136 (matches global contiguity). Epilogue writes
// fp16 K (s-major) / V (d-major).
// ---------------------------------------------------------------------------
#define NSTAGE   4
#define A_ST_U32 (128 * 20)
#define B_ST_U32 (16 * 136)
#define KV_SMEM  (NSTAGE * (A_ST_U32 + B_ST_U32) * 4)   // 75776 bytes

__global__ __launch_bounds__(256)
void gemm_kv_f16(const __half* __restrict__ A16,      // [1024][512]
                 const uint32_t* __restrict__ Bp,     // [16][256][4096] pairs
                 __half* __restrict__ gk,             // (bh,s,d)
                 __half* __restrict__ gv)             // (bh,d,s)
{
    extern __shared__ uint32_t smdyn[];
    uint32_t (*As)[128][20]  = (uint32_t(*)[128][20])smdyn;
    uint32_t (*Bs)[16][136]  = (uint32_t(*)[16][136])(smdyn + NSTAGE * A_ST_U32);

    const int b  = blockIdx.z;
    const int m0 = blockIdx.y * 128;
    const int n0 = blockIdx.x * 128;
    const uint32_t* Ap = (const uint32_t*)A16;               // pair view [1024][256]
    const uint32_t* Bb = Bp + (long)b * (C_ / 2) * S_;

    const int tid  = threadIdx.x;
    const int warp = tid >> 5;
    const int lane = tid & 31;
    const int wm   = (warp >> 1) * 32;
    const int wn   = (warp & 1) * 64;
    const int g    = lane >> 2;
    const int tg   = lane & 3;

    float acc[2][8][4];
    #pragma unroll
    for (int mt = 0; mt < 2; mt++)
        #pragma unroll
        for (int nt = 0; nt < 8; nt++)
            #pragma unroll
            for (int i = 0; i < 4; i++)
                acc[mt][nt][i] = 0.f;

    // async stage loader: chunk ch (16 k-pairs) -> stage st
    auto issue = [&](int ch, int st) {
        const int kc2 = ch * 16;
        #pragma unroll
        for (int t = 0; t < 2; t++) {            // A: 512 x 16B
            const int idx = tid + t * 256;
            const int r = idx >> 2, p4 = (idx & 3) * 4;
            const uint32_t* src = &Ap[(long)(m0 + r) * (C_ / 2) + kc2 + p4];
            const uint32_t d = smem_u32(&As[st][r][p4]);
            asm volatile("cp.async.cg.shared.global [%0], [%1], 16;" :: "r"(d), "l"(src));
        }
        #pragma unroll
        for (int t = 0; t < 2; t++) {            // B: 512 x 16B
            const int idx = tid + t * 256;
            const int r = idx >> 5, c4 = (idx & 31) * 4;
            const uint32_t* src = &Bb[(long)(kc2 + r) * S_ + n0 + c4];
            const uint32_t d = smem_u32(&Bs[st][r][c4]);
            asm volatile("cp.async.cg.shared.global [%0], [%1], 16;" :: "r"(d), "l"(src));
        }
        asm volatile("cp.async.commit_group;" ::: "memory");
    };

    issue(0, 0); issue(1, 1); issue(2, 2);

    const int NCH = C_ / 32;   // 16
    for (int ch = 0; ch < NCH; ++ch) {
        const int st = ch & (NSTAGE - 1);
        asm volatile("cp.async.wait_group 2;" ::: "memory");
        __syncthreads();

        #pragma unroll
        for (int ks = 0; ks < 2; ks++) {
            const int kb = ks * 8;
            uint32_t bf[8][2];
            #pragma unroll
            for (int nt = 0; nt < 8; nt++) {
                bf[nt][0] = Bs[st][kb + tg]    [wn + nt * 8 + g];
                bf[nt][1] = Bs[st][kb + tg + 4][wn + nt * 8 + g];
            }
            #pragma unroll
            for (int mt = 0; mt < 2; mt++) {
                const int mi = wm + mt * 16 + g;
                uint32_t a0 = As[st][mi]    [kb + tg];
                uint32_t a1 = As[st][mi + 8][kb + tg];
                uint32_t a2 = As[st][mi]    [kb + tg + 4];
                uint32_t a3 = As[st][mi + 8][kb + tg + 4];
                #pragma unroll
                for (int nt = 0; nt < 8; nt++) {
                    asm volatile(
                        "mma.sync.aligned.m16n8k16.row.col.f32.f16.f16.f32 "
                        "{%0,%1,%2,%3}, {%4,%5,%6,%7}, {%8,%9}, {%0,%1,%2,%3};"
                        : "+f"(acc[mt][nt][0]), "+f"(acc[mt][nt][1]),
                          "+f"(acc[mt][nt][2]), "+f"(acc[mt][nt][3])
                        : "r"(a0), "r"(a1), "r"(a2), "r"(a3),
                          "r"(bf[nt][0]), "r"(bf[nt][1]));
                }
            }
        }

        if (ch + NSTAGE - 1 < NCH)
            issue(ch + NSTAGE - 1, (ch + NSTAGE - 1) & (NSTAGE - 1));
    }

    // epilogue: K rows (m<512) -> (bh,s,d) scalar halves; V rows -> (bh,d,s) half2
    #pragma unroll
    for (int mt = 0; mt < 2; mt++) {
        const int mA = m0 + wm + mt * 16 + g;
        const int mB = mA + 8;
        #pragma unroll
        for (int nt = 0; nt < 8; nt++) {
            const int col = n0 + wn + nt * 8 + 2 * tg;
            if (m0 < 512) {
                const int hA = mA >> 6, dA = mA & 63;
                const int hB = mB >> 6, dB = mB & 63;
                __half* pA = gk + ((long)(b * 8 + hA) * S_ + col) * DIMH + dA;
                __half* pB = gk + ((long)(b * 8 + hB) * S_ + col) * DIMH + dB;
                pA[0]    = __float2half_rn(acc[mt][nt][0]);
                pA[DIMH] = __float2half_rn(acc[mt][nt][1]);
                pB[0]    = __float2half_rn(acc[mt][nt][2]);
                pB[DIMH] = __float2half_rn(acc[mt][nt][3]);
            } else {
                const int m2A = mA - 512, m2B = mB - 512;
                const int hA = m2A >> 6, dA = m2A & 63;
                const int hB = m2B >> 6, dB = m2B & 63;
                *(uint32_t*)(gv + ((long)(b * 8 + hA) * DIMH + dA) * S_ + col) =
                    f2h2(acc[mt][nt][0], acc[mt][nt][1]);
                *(uint32_t*)(gv + ((long)(b * 8 + hB) * DIMH + dB) * S_ + col) =
                    f2h2(acc[mt][nt][2], acc[mt][nt][3]);
            }
        }
    }
}

// ---------------------------------------------------------------------------
// fp32 SGEMM (q / output projections).  C[M,N] = A[M,K] * B^T.
// ---------------------------------------------------------------------------
__global__ __launch_bounds__(256, 2)
void sgemm_nt(const float* __restrict__ A, const float* __restrict__ B,
              float* __restrict__ C, int M, int N, int K)
{
    __shared__ float As[8][132];
    __shared__ float Bs[8][132];

    const int tid  = threadIdx.x;
    const int tx   = tid & 15;
    const int ty   = tid >> 4;
    const int m0   = blockIdx.y * 128;
    const int n0   = blockIdx.x * 128;
    const int lrow = tid >> 1;
    const int lcol = (tid & 1) * 4;

    float acc[2][2][4][4];
    #pragma unroll
    for (int qm = 0; qm < 2; qm++)
        #pragma unroll
        for (int qn = 0; qn < 2; qn++)
            #pragma unroll
            for (int i = 0; i < 4; i++)
                #pragma unroll
                for (int j = 0; j < 4; j++)
                    acc[qm][qn][i][j] = 0.f;

    const int kIter = K >> 3;
    float4 av = *(const float4*)&A[(long)(m0 + lrow) * K + lcol];
    float4 bv = *(const float4*)&B[(long)(n0 + lrow) * K + lcol];

    for (int it = 0; it < kIter; ++it) {
        __syncthreads();
        As[lcol + 0][lrow] = av.x; As[lcol + 1][lrow] = av.y;
        As[lcol + 2][lrow] = av.z; As[lcol + 3][lrow] = av.w;
        Bs[lcol + 0][lrow] = bv.x; Bs[lcol + 1][lrow] = bv.y;
        Bs[lcol + 2][lrow] = bv.z; Bs[lcol + 3][lrow] = bv.w;
        __syncthreads();

        if (it + 1 < kIter) {
            const int k0 = (it + 1) << 3;
            av = *(const float4*)&A[(long)(m0 + lrow) * K + k0 + lcol];
            bv = *(const float4*)&B[(long)(n0 + lrow) * K + k0 + lcol];
        }

        #pragma unroll
        for (int kk = 0; kk < 8; kk++) {
            float4 a0 = *(const float4*)&As[kk][ty * 4];
            float4 a1 = *(const float4*)&As[kk][64 + ty * 4];
            float4 b0 = *(const float4*)&Bs[kk][tx * 4];
            float4 b1 = *(const float4*)&Bs[kk][64 + tx * 4];
            float ar[2][4] = {{a0.x, a0.y, a0.z, a0.w}, {a1.x, a1.y, a1.z, a1.w}};
            float br[2][4] = {{b0.x, b0.y, b0.z, b0.w}, {b1.x, b1.y, b1.z, b1.w}};
            #pragma unroll
            for (int qm = 0; qm < 2; qm++)
                #pragma unroll
                for (int i = 0; i < 4; i++)
                    #pragma unroll
                    for (int qn = 0; qn < 2; qn++)
                        #pragma unroll
                        for (int j = 0; j < 4; j++)
                            acc[qm][qn][i][j] += ar[qm][i] * br[qn][j];
        }
    }

    #pragma unroll
    for (int qm = 0; qm < 2; qm++)
        #pragma unroll
        for (int i = 0; i < 4; i++) {
            const long row = m0 + qm * 64 + ty * 4 + i;
            #pragma unroll
            for (int qn = 0; qn < 2; qn++) {
                float4 w = make_float4(acc[qm][qn][i][0], acc[qm][qn][i][1],
                                       acc[qm][qn][i][2], acc[qm][qn][i][3]);
                *(float4*)&C[row * N + n0 + qn * 64 + tx * 4] = w;
            }
        }
}

// ---------------------------------------------------------------------------
// Tensor-core flash attention, split-KV (unchanged from R7 pass).
// ---------------------------------------------------------------------------
#define KS_STRIDE 72     // halves per K/Q smem row
#define VS_STRIDE 136    // halves per V smem row

__global__ __launch_bounds__(128)
void attn_f16(const __half* __restrict__ q16, const __half* __restrict__ k16,
              const __half* __restrict__ v16, float* __restrict__ opart,
              float* __restrict__ ml)
{
    __shared__ __half Qs[T_ * KS_STRIDE];       // 64 x 72
    __shared__ __half Ks[128 * KS_STRIDE];      // 128 x 72
    __shared__ __half Vs[DIMH * VS_STRIDE];     // 64 x 136

    const int sp  = blockIdx.x;
    const int bh  = blockIdx.y;
    const int tid = threadIdx.x;
    const int warp = tid >> 5;
    const int lane = tid & 31;
    const int g   = lane >> 2;
    const int tg  = lane & 3;
    const int wm  = warp * 16;

    // stage Q (64 x 64 halves)
    const __half* qb = q16 + (long)bh * T_ * DIMH;
    #pragma unroll
    for (int t = 0; t < 4; t++) {
        const int idx = tid + t * 128;
        const int r = idx >> 3, c8 = idx & 7;
        *(uint4*)&Qs[r * KS_STRIDE + c8 * 8] = *(const uint4*)&qb[r * DIMH + c8 * 8];
    }
    __syncthreads();

    // Q fragments: 4 k-steps over d
    uint32_t aq[4][4];
    #pragma unroll
    for (int ks = 0; ks < 4; ks++) {
        aq[ks][0] = *(const uint32_t*)&Qs[(wm + g)     * KS_STRIDE + ks * 16 + 2 * tg];
        aq[ks][1] = *(const uint32_t*)&Qs[(wm + g + 8) * KS_STRIDE + ks * 16 + 2 * tg];
        aq[ks][2] = *(const uint32_t*)&Qs[(wm + g)     * KS_STRIDE + ks * 16 + 2 * tg + 8];
        aq[ks][3] = *(const uint32_t*)&Qs[(wm + g + 8) * KS_STRIDE + ks * 16 + 2 * tg + 8];
    }

    float accO[8][4];
    #pragma unroll
    for (int nt = 0; nt < 8; nt++)
        #pragma unroll
        for (int i = 0; i < 4; i++) accO[nt][i] = 0.f;
    float m0r = -1e30f, m1r = -1e30f, l0 = 0.f, l1 = 0.f;

    const __half* kb = k16 + ((long)bh * S_ + sp * S_PER) * DIMH;
    const __half* vb = v16 + (long)bh * DIMH * S_ + sp * S_PER;

    for (int tile = 0; tile < S_PER / 128; tile++) {
        __syncthreads();
        #pragma unroll
        for (int t = 0; t < 8; t++) {            // K: 128 x 64 halves
            const int idx = tid + t * 128;
            const int r = idx >> 3, c8 = idx & 7;
            *(uint4*)&Ks[r * KS_STRIDE + c8 * 8] =
                *(const uint4*)&kb[(long)(tile * 128 + r) * DIMH + c8 * 8];
        }
        #pragma unroll
        for (int t = 0; t < 8; t++) {            // V: 64 x 128 halves
            const int idx = tid + t * 128;
            const int r = idx >> 4, c16 = idx & 15;
            *(uint4*)&Vs[r * VS_STRIDE + c16 * 8] =
                *(const uint4*)&vb[(long)r * S_ + tile * 128 + c16 * 8];
        }
        __syncthreads();

        // QK^T: scores 16 rows x 128 cols per warp
        float accS[16][4];
        #pragma unroll
        for (int nt = 0; nt < 16; nt++)
            #pragma unroll
            for (int i = 0; i < 4; i++) accS[nt][i] = 0.f;

        #pragma unroll
        for (int ks = 0; ks < 4; ks++) {
            #pragma unroll
            for (int nt = 0; nt < 16; nt++) {
                uint32_t b0 = *(const uint32_t*)&Ks[(nt * 8 + g) * KS_STRIDE + ks * 16 + 2 * tg];
                uint32_t b1 = *(const uint32_t*)&Ks[(nt * 8 + g) * KS_STRIDE + ks * 16 + 2 * tg + 8];
                asm volatile(
                    "mma.sync.aligned.m16n8k16.row.col.f32.f16.f16.f32 "
                    "{%0,%1,%2,%3}, {%4,%5,%6,%7}, {%8,%9}, {%0,%1,%2,%3};"
                    : "+f"(accS[nt][0]), "+f"(accS[nt][1]),
                      "+f"(accS[nt][2]), "+f"(accS[nt][3])
                    : "r"(aq[ks][0]), "r"(aq[ks][1]), "r"(aq[ks][2]), "r"(aq[ks][3]),
                      "r"(b0), "r"(b1));
            }
        }

        // online softmax (rows g and g+8)
        float mx0 = -1e30f, mx1 = -1e30f;
        #pragma unroll
        for (int nt = 0; nt < 16; nt++) {
            mx0 = fmaxf(mx0, fmaxf(accS[nt][0], accS[nt][1]));
            mx1 = fmaxf(mx1, fmaxf(accS[nt][2], accS[nt][3]));
        }
        mx0 = fmaxf(mx0, __shfl_xor_sync(0xffffffffu, mx0, 1));
        mx0 = fmaxf(mx0, __shfl_xor_sync(0xffffffffu, mx0, 2));
        mx1 = fmaxf(mx1, __shfl_xor_sync(0xffffffffu, mx1, 1));
        mx1 = fmaxf(mx1, __shfl_xor_sync(0xffffffffu, mx1, 2));

        const float mn0 = fmaxf(m0r, mx0);
        const float mn1 = fmaxf(m1r, mx1);
        const float cr0 = __expf(m0r - mn0);
        const float cr1 = __expf(m1r - mn1);
        m0r = mn0; m1r = mn1;

        float s0 = 0.f, s1 = 0.f;
        #pragma unroll
        for (int nt = 0; nt < 16; nt++) {
            accS[nt][0] = __expf(accS[nt][0] - mn0);
            accS[nt][1] = __expf(accS[nt][1] - mn0);
            accS[nt][2] = __expf(accS[nt][2] - mn1);
            accS[nt][3] = __expf(accS[nt][3] - mn1);
            s0 += accS[nt][0] + accS[nt][1];
            s1 += accS[nt][2] + accS[nt][3];
        }
        s0 += __shfl_xor_sync(0xffffffffu, s0, 1);
        s0 += __shfl_xor_sync(0xffffffffu, s0, 2);
        s1 += __shfl_xor_sync(0xffffffffu, s1, 1);
        s1 += __shfl_xor_sync(0xffffffffu, s1, 2);
        l0 = l0 * cr0 + s0;
        l1 = l1 * cr1 + s1;

        #pragma unroll
        for (int nt = 0; nt < 8; nt++) {
            accO[nt][0] *= cr0; accO[nt][1] *= cr0;
            accO[nt][2] *= cr1; accO[nt][3] *= cr1;
        }

        // P -> half2 A-fragments (k = s, 8 k-steps)
        uint32_t ap[8][4];
        #pragma unroll
        for (int ks = 0; ks < 8; ks++) {
            ap[ks][0] = f2h2(accS[2*ks][0],   accS[2*ks][1]);
            ap[ks][1] = f2h2(accS[2*ks][2],   accS[2*ks][3]);
            ap[ks][2] = f2h2(accS[2*ks+1][0], accS[2*ks+1][1]);
            ap[ks][3] = f2h2(accS[2*ks+1][2], accS[2*ks+1][3]);
        }

        // P @ V
        #pragma unroll
        for (int ks = 0; ks < 8; ks++) {
            #pragma unroll
            for (int nt = 0; nt < 8; nt++) {
                uint32_t b0 = *(const uint32_t*)&Vs[(nt * 8 + g) * VS_STRIDE + ks * 16 + 2 * tg];
                uint32_t b1 = *(const uint32_t*)&Vs[(nt * 8 + g) * VS_STRIDE + ks * 16 + 2 * tg + 8];
                asm volatile(
                    "mma.sync.aligned.m16n8k16.row.col.f32.f16.f16.f32 "
                    "{%0,%1,%2,%3}, {%4,%5,%6,%7}, {%8,%9}, {%0,%1,%2,%3};"
                    : "+f"(accO[nt][0]), "+f"(accO[nt][1]),
                      "+f"(accO[nt][2]), "+f"(accO[nt][3])
                    : "r"(ap[ks][0]), "r"(ap[ks][1]), "r"(ap[ks][2]), "r"(ap[ks][3]),
                      "r"(b0), "r"(b1));
            }
        }
    }

    // write partials (unnormalized) + (m, l)
    float* op = opart + ((long)(sp * BH_ + bh) * T_) * DIMH;
    const int rA = wm + g, rB = wm + g + 8;
    #pragma unroll
    for (int nt = 0; nt < 8; nt++) {
        const int col = nt * 8 + 2 * tg;
        *(float2*)&op[rA * DIMH + col] = make_float2(accO[nt][0], accO[nt][1]);
        *(float2*)&op[rB * DIMH + col] = make_float2(accO[nt][2], accO[nt][3]);
    }
    if (tg == 0) {
        float* mlp = ml + ((long)(sp * BH_ + bh) * T_) * 2;
        mlp[rA * 2] = m0r; mlp[rA * 2 + 1] = l0;
        mlp[rB * 2] = m1r; mlp[rB * 2 + 1] = l1;
    }
}

// ---------------------------------------------------------------------------
// split-KV combine -> g_ao (B,T,inner)
// ---------------------------------------------------------------------------
__global__ void attn_combine(const float* __restrict__ opart,
                             const float* __restrict__ ml, float* __restrict__ ao)
{
    const int bh  = blockIdx.x;
    const int b   = bh >> 3;
    const int h   = bh & 7;
    const int tid = threadIdx.x;       // 128
    const int t   = tid >> 1;
    const int d0  = (tid & 1) * 32;

    float m[SPLIT], l[SPLIT];
    float M = -1e30f;
    #pragma unroll
    for (int i = 0; i < SPLIT; i++) {
        m[i] = ml[((long)(i * BH_ + bh) * T_ + t) * 2];
        l[i] = ml[((long)(i * BH_ + bh) * T_ + t) * 2 + 1];
        M = fmaxf(M, m[i]);
    }
    float w[SPLIT], L = 0.f;
    #pragma unroll
    for (int i = 0; i < SPLIT; i++) {
        w[i] = __expf(m[i] - M);
        L += w[i] * l[i];
    }
    const float inv = 1.f / L;

    float* dst = ao + ((long)(b * T_ + t)) * INNER + h * DIMH + d0;
    #pragma unroll
    for (int d = 0; d < 32; d++) {
        float o = 0.f;
        #pragma unroll
        for (int i = 0; i < SPLIT; i++)
            o += w[i] * opart[((long)(i * BH_ + bh) * T_ + t) * DIMH + d0 + d];
        dst[d] = o * inv;
    }
}

// ---------------------------------------------------------------------------
extern "C" void kernel_launch(void* const* d_in, const int* in_sizes, int n_in,
                              void* d_out, int out_size)
{
    const float* vis  = (const float*)d_in[0];
    const float* lang = (const float*)d_in[1];
    // d_in[2] = mask (unused)
    const float* Wq   = (const float*)d_in[3];
    const float* Wk   = (const float*)d_in[4];
    const float* Wv   = (const float*)d_in[5];
    const float* Wo   = (const float*)d_in[6];
    float* out = (float*)d_out;

    float *q, *ao, *op, *ml;
    __half *w16, *q16, *k16, *v16;
    uint32_t* v16p;
    cudaGetSymbolAddress((void**)&q,    g_q);
    cudaGetSymbolAddress((void**)&ao,   g_ao);
    cudaGetSymbolAddress((void**)&w16,  g_w16);
    cudaGetSymbolAddress((void**)&v16p, g_v16p);
    cudaGetSymbolAddress((void**)&q16,  g_q16);
    cudaGetSymbolAddress((void**)&k16,  g_k16);
    cudaGetSymbolAddress((void**)&v16,  g_v16);
    cudaGetSymbolAddress((void**)&op,   g_op);
    cudaGetSymbolAddress((void**)&ml,   g_ml);

    cudaFuncSetAttribute(gemm_kv_f16, cudaFuncAttributeMaxDynamicSharedMemorySize,
                         KV_SMEM);

    // prep
    prep_w16<<<INNER * C_ / 256, 256>>>(Wk, Wv, w16);
    prep_vis16<<<(int)(((long)B_ * (C_ / 2) * S_) / 256), 256>>>(vis, v16p);

    // q projection (fp32 SIMT) then fp16 repack
    sgemm_nt<<<dim3(INNER / 128, (B_ * T_) / 128), 256>>>(lang, Wq, q, B_ * T_, INNER, C_);
    prep_q16<<<B_ * T_ * INNER / 256, 256>>>(q, q16);

    // fused k+v projection (fp16 tensor cores, cp.async pipeline)
    gemm_kv_f16<<<dim3(S_ / 128, (2 * INNER) / 128, B_), 256, KV_SMEM>>>(w16, v16p, k16, v16);

    // flash attention (tensor cores, split-KV) + combine
    attn_f16<<<dim3(SPLIT, BH_), 128>>>(q16, k16, v16, op, ml);
    attn_combine<<<BH_, 128>>>(op, ml, ao);

    // output projection (fp32 SIMT)
    sgemm_nt<<<dim3(C_ / 128, (B_ * T_) / 128), 256>>>(ao, Wo, out, B_ * T_, C_, INNER);
}

// round 10
// speedup vs baseline: 8.6943x; 1.1951x over previous
#include <cuda_runtime.h>
#include <cuda_fp16.h>
#include <cstdint>

// Problem constants
#define B_    16
#define T_    64
#define C_    512
#define S_    4096
#define INNER 512
#define DIMH  64
#define NHEAD 8
#define BH_   (B_ * NHEAD)
#define SPLIT 4
#define S_PER (S_ / SPLIT)      // 1024

// Scratch (device globals; no allocations allowed)
__device__ float    g_q    [B_ * T_ * INNER];             // q projection f32
__device__ float    g_ao   [B_ * T_ * INNER];             // attention out f32
__device__ __half   g_w16  [2 * INNER * C_];              // concat(Wk,Wv) fp16
__device__ __half   g_lang16[B_ * T_ * C_];               // lang fp16 [1024][512]
__device__ __half   g_ao16 [B_ * T_ * INNER];             // attention out fp16
__device__ uint32_t g_wqT  [(C_ / 2) * INNER];            // Wq^T pair-packed [256][512]
__device__ uint32_t g_woT  [(INNER / 2) * C_];            // Wo^T pair-packed [256][512]
__device__ uint32_t g_v16p [(long)B_ * (C_ / 2) * S_];    // vis fp16 pair-packed
__device__ __half   g_q16  [BH_ * T_ * DIMH];             // q fp16 (bh,t,d), pre-scaled
__device__ __half   g_k16  [(long)BH_ * S_ * DIMH];       // K fp16 s-major (bh,s,d)
__device__ __half   g_v16  [(long)BH_ * DIMH * S_];       // V fp16 d-major (bh,d,s)
__device__ float    g_op   [(long)SPLIT * BH_ * T_ * DIMH]; // partial O
__device__ float    g_ml   [SPLIT * BH_ * T_ * 2];        // partial (m,l)

// pack two fp32 -> one .f16x2 register (lo = first arg)
__device__ __forceinline__ uint32_t f2h2(float lo, float hi) {
    uint32_t r;
    asm("cvt.rn.f16x2.f32 %0, %1, %2;" : "=r"(r) : "f"(hi), "f"(lo));
    return r;
}

__device__ __forceinline__ uint32_t smem_u32(const void* p) {
    uint32_t a;
    asm("{ .reg .u64 t; cvta.to.shared.u64 t, %1; cvt.u32.u64 %0, t; }" : "=r"(a) : "l"(p));
    return a;
}

// ---------------------------------------------------------------------------
__global__ void conv16(const float* __restrict__ src, __half* __restrict__ dst)
{
    const int i = blockIdx.x * 256 + threadIdx.x;
    dst[i] = __float2half_rn(src[i]);
}

// W [512][512] row-major f32 -> pair-packed transpose [k2][n]: vp[k2*512+n] =
// pack(W[n][2k2], W[n][2k2+1])
__global__ void packT(const float* __restrict__ W, uint32_t* __restrict__ vp)
{
    const int idx = blockIdx.x * 256 + threadIdx.x;   // 0..131071 = k2*512 + n
    const int n  = idx & 511;
    const int k2 = idx >> 9;
    const float* s = W + n * 512 + 2 * k2;
    vp[idx] = f2h2(s[0], s[1]);
}

__global__ void prep_w16(const float* __restrict__ Wk, const float* __restrict__ Wv,
                         __half* __restrict__ w16)
{
    const int i = blockIdx.x * 256 + threadIdx.x;
    w16[i]              = __float2half_rn(Wk[i]);
    w16[INNER * C_ + i] = __float2half_rn(Wv[i]);
}

__global__ void prep_vis16(const float* __restrict__ vis, uint32_t* __restrict__ vp)
{
    const long i  = (long)blockIdx.x * 256 + threadIdx.x;
    const long s  = i & (S_ - 1);
    const long c2 = (i >> 12) & 255;
    const long b  = i >> 20;
    const float* src = vis + (((b * C_) + 2 * c2) << 12) + s;
    vp[i] = f2h2(src[0], src[S_]);
}

// q f32 (B,T,inner) -> q16 (bh,t,d), scaled by 0.125   [validated in R8]
__global__ void prep_q16(const float* __restrict__ q, __half* __restrict__ q16)
{
    const int i = blockIdx.x * 256 + threadIdx.x;   // 0 .. 524287
    const int d = i & 63;
    const int h = (i >> 6) & 7;
    const int t = (i >> 9) & 63;
    const int b = i >> 15;
    q16[(((b * 8 + h) * T_) + t) * DIMH + d] = __float2half_rn(q[i] * 0.125f);
}

// ---------------------------------------------------------------------------
// shared tile sizes (kv kernel + its clone)
#define NSTAGE   4
#define A_ST_U32 (128 * 20)
#define B_ST_U32 (16 * 136)
#define KV_SMEM  (NSTAGE * (A_ST_U32 + B_ST_U32) * 4)   // 75776 bytes

// ---------------------------------------------------------------------------
// Projection GEMM: Cf[1024][512] = A16[1024][512] @ (packed B)[512][512]
// Verbatim clone of gemm_kv_f16 mainloop with N=512 and f32 epilogue.
// ---------------------------------------------------------------------------
__global__ __launch_bounds__(256)
void gemm_proj(const __half* __restrict__ A16,      // [1024][512]
               const uint32_t* __restrict__ Bp,     // [256][512] pairs k2-major
               float* __restrict__ Cf)              // [1024][512]
{
    extern __shared__ uint32_t smdyn[];
    uint32_t (*As)[128][20]  = (uint32_t(*)[128][20])smdyn;
    uint32_t (*Bs)[16][136]  = (uint32_t(*)[16][136])(smdyn + NSTAGE * A_ST_U32);

    const int m0 = blockIdx.y * 128;
    const int n0 = blockIdx.x * 128;
    const uint32_t* Ap = (const uint32_t*)A16;               // pair view [1024][256]

    const int tid  = threadIdx.x;
    const int warp = tid >> 5;
    const int lane = tid & 31;
    const int wm   = (warp >> 1) * 32;
    const int wn   = (warp & 1) * 64;
    const int g    = lane >> 2;
    const int tg   = lane & 3;

    float acc[2][8][4];
    #pragma unroll
    for (int mt = 0; mt < 2; mt++)
        #pragma unroll
        for (int nt = 0; nt < 8; nt++)
            #pragma unroll
            for (int i = 0; i < 4; i++)
                acc[mt][nt][i] = 0.f;

    auto issue = [&](int ch, int st) {
        const int kc2 = ch * 16;
        #pragma unroll
        for (int t = 0; t < 2; t++) {            // A: 512 x 16B
            const int idx = tid + t * 256;
            const int r = idx >> 2, p4 = (idx & 3) * 4;
            const uint32_t* src = &Ap[(long)(m0 + r) * (C_ / 2) + kc2 + p4];
            asm volatile("cp.async.cg.shared.global [%0], [%1], 16;"
                         :: "r"(smem_u32(&As[st][r][p4])), "l"(src));
        }
        #pragma unroll
        for (int t = 0; t < 2; t++) {            // B: 512 x 16B
            const int idx = tid + t * 256;
            const int r = idx >> 5, c4 = (idx & 31) * 4;
            const uint32_t* src = &Bp[(long)(kc2 + r) * 512 + n0 + c4];
            asm volatile("cp.async.cg.shared.global [%0], [%1], 16;"
                         :: "r"(smem_u32(&Bs[st][r][c4])), "l"(src));
        }
        asm volatile("cp.async.commit_group;" ::: "memory");
    };

    issue(0, 0); issue(1, 1); issue(2, 2);

    const int NCH = C_ / 32;   // 16
    for (int ch = 0; ch < NCH; ++ch) {
        const int st = ch & (NSTAGE - 1);
        asm volatile("cp.async.wait_group 2;" ::: "memory");
        __syncthreads();

        #pragma unroll
        for (int ks = 0; ks < 2; ks++) {
            const int kb = ks * 8;
            uint32_t bf[8][2];
            #pragma unroll
            for (int nt = 0; nt < 8; nt++) {
                bf[nt][0] = Bs[st][kb + tg]    [wn + nt * 8 + g];
                bf[nt][1] = Bs[st][kb + tg + 4][wn + nt * 8 + g];
            }
            #pragma unroll
            for (int mt = 0; mt < 2; mt++) {
                const int mi = wm + mt * 16 + g;
                uint32_t a0 = As[st][mi]    [kb + tg];
                uint32_t a1 = As[st][mi + 8][kb + tg];
                uint32_t a2 = As[st][mi]    [kb + tg + 4];
                uint32_t a3 = As[st][mi + 8][kb + tg + 4];
                #pragma unroll
                for (int nt = 0; nt < 8; nt++) {
                    asm volatile(
                        "mma.sync.aligned.m16n8k16.row.col.f32.f16.f16.f32 "
                        "{%0,%1,%2,%3}, {%4,%5,%6,%7}, {%8,%9}, {%0,%1,%2,%3};"
                        : "+f"(acc[mt][nt][0]), "+f"(acc[mt][nt][1]),
                          "+f"(acc[mt][nt][2]), "+f"(acc[mt][nt][3])
                        : "r"(a0), "r"(a1), "r"(a2), "r"(a3),
                          "r"(bf[nt][0]), "r"(bf[nt][1]));
                }
            }
        }

        if (ch + NSTAGE - 1 < NCH)
            issue(ch + NSTAGE - 1, (ch + NSTAGE - 1) & (NSTAGE - 1));
    }

    #pragma unroll
    for (int mt = 0; mt < 2; mt++) {
        const int rA = m0 + wm + mt * 16 + g;
        const int rB = rA + 8;
        #pragma unroll
        for (int nt = 0; nt < 8; nt++) {
            const int col = n0 + wn + nt * 8 + 2 * tg;
            *(float2*)&Cf[(long)rA * 512 + col] = make_float2(acc[mt][nt][0], acc[mt][nt][1]);
            *(float2*)&Cf[(long)rB * 512 + col] = make_float2(acc[mt][nt][2], acc[mt][nt][3]);
        }
    }
}

// ---------------------------------------------------------------------------
// Fused k/v projection, fp16 mma, 4-stage cp.async (unchanged from R8 pass).
// ---------------------------------------------------------------------------
__global__ __launch_bounds__(256)
void gemm_kv_f16(const __half* __restrict__ A16,      // [1024][512]
                 const uint32_t* __restrict__ Bp,     // [16][256][4096] pairs
                 __half* __restrict__ gk,             // (bh,s,d)
                 __half* __restrict__ gv)             // (bh,d,s)
{
    extern __shared__ uint32_t smdyn[];
    uint32_t (*As)[128][20]  = (uint32_t(*)[128][20])smdyn;
    uint32_t (*Bs)[16][136]  = (uint32_t(*)[16][136])(smdyn + NSTAGE * A_ST_U32);

    const int b  = blockIdx.z;
    const int m0 = blockIdx.y * 128;
    const int n0 = blockIdx.x * 128;
    const uint32_t* Ap = (const uint32_t*)A16;               // pair view [1024][256]
    const uint32_t* Bb = Bp + (long)b * (C_ / 2) * S_;

    const int tid  = threadIdx.x;
    const int warp = tid >> 5;
    const int lane = tid & 31;
    const int wm   = (warp >> 1) * 32;
    const int wn   = (warp & 1) * 64;
    const int g    = lane >> 2;
    const int tg   = lane & 3;

    float acc[2][8][4];
    #pragma unroll
    for (int mt = 0; mt < 2; mt++)
        #pragma unroll
        for (int nt = 0; nt < 8; nt++)
            #pragma unroll
            for (int i = 0; i < 4; i++)
                acc[mt][nt][i] = 0.f;

    auto issue = [&](int ch, int st) {
        const int kc2 = ch * 16;
        #pragma unroll
        for (int t = 0; t < 2; t++) {            // A: 512 x 16B
            const int idx = tid + t * 256;
            const int r = idx >> 2, p4 = (idx & 3) * 4;
            const uint32_t* src = &Ap[(long)(m0 + r) * (C_ / 2) + kc2 + p4];
            asm volatile("cp.async.cg.shared.global [%0], [%1], 16;"
                         :: "r"(smem_u32(&As[st][r][p4])), "l"(src));
        }
        #pragma unroll
        for (int t = 0; t < 2; t++) {            // B: 512 x 16B
            const int idx = tid + t * 256;
            const int r = idx >> 5, c4 = (idx & 31) * 4;
            const uint32_t* src = &Bb[(long)(kc2 + r) * S_ + n0 + c4];
            asm volatile("cp.async.cg.shared.global [%0], [%1], 16;"
                         :: "r"(smem_u32(&Bs[st][r][c4])), "l"(src));
        }
        asm volatile("cp.async.commit_group;" ::: "memory");
    };

    issue(0, 0); issue(1, 1); issue(2, 2);

    const int NCH = C_ / 32;   // 16
    for (int ch = 0; ch < NCH; ++ch) {
        const int st = ch & (NSTAGE - 1);
        asm volatile("cp.async.wait_group 2;" ::: "memory");
        __syncthreads();

        #pragma unroll
        for (int ks = 0; ks < 2; ks++) {
            const int kb = ks * 8;
            uint32_t bf[8][2];
            #pragma unroll
            for (int nt = 0; nt < 8; nt++) {
                bf[nt][0] = Bs[st][kb + tg]    [wn + nt * 8 + g];
                bf[nt][1] = Bs[st][kb + tg + 4][wn + nt * 8 + g];
            }
            #pragma unroll
            for (int mt = 0; mt < 2; mt++) {
                const int mi = wm + mt * 16 + g;
                uint32_t a0 = As[st][mi]    [kb + tg];
                uint32_t a1 = As[st][mi + 8][kb + tg];
                uint32_t a2 = As[st][mi]    [kb + tg + 4];
                uint32_t a3 = As[st][mi + 8][kb + tg + 4];
                #pragma unroll
                for (int nt = 0; nt < 8; nt++) {
                    asm volatile(
                        "mma.sync.aligned.m16n8k16.row.col.f32.f16.f16.f32 "
                        "{%0,%1,%2,%3}, {%4,%5,%6,%7}, {%8,%9}, {%0,%1,%2,%3};"
                        : "+f"(acc[mt][nt][0]), "+f"(acc[mt][nt][1]),
                          "+f"(acc[mt][nt][2]), "+f"(acc[mt][nt][3])
                        : "r"(a0), "r"(a1), "r"(a2), "r"(a3),
                          "r"(bf[nt][0]), "r"(bf[nt][1]));
                }
            }
        }

        if (ch + NSTAGE - 1 < NCH)
            issue(ch + NSTAGE - 1, (ch + NSTAGE - 1) & (NSTAGE - 1));
    }

    // epilogue: K rows (m<512) -> (bh,s,d) scalar halves; V rows -> (bh,d,s) half2
    #pragma unroll
    for (int mt = 0; mt < 2; mt++) {
        const int mA = m0 + wm + mt * 16 + g;
        const int mB = mA + 8;
        #pragma unroll
        for (int nt = 0; nt < 8; nt++) {
            const int col = n0 + wn + nt * 8 + 2 * tg;
            if (m0 < 512) {
                const int hA = mA >> 6, dA = mA & 63;
                const int hB = mB >> 6, dB = mB & 63;
                __half* pA = gk + ((long)(b * 8 + hA) * S_ + col) * DIMH + dA;
                __half* pB = gk + ((long)(b * 8 + hB) * S_ + col) * DIMH + dB;
                pA[0]    = __float2half_rn(acc[mt][nt][0]);
                pA[DIMH] = __float2half_rn(acc[mt][nt][1]);
                pB[0]    = __float2half_rn(acc[mt][nt][2]);
                pB[DIMH] = __float2half_rn(acc[mt][nt][3]);
            } else {
                const int m2A = mA - 512, m2B = mB - 512;
                const int hA = m2A >> 6, dA = m2A & 63;
                const int hB = m2B >> 6, dB = m2B & 63;
                *(uint32_t*)(gv + ((long)(b * 8 + hA) * DIMH + dA) * S_ + col) =
                    f2h2(acc[mt][nt][0], acc[mt][nt][1]);
                *(uint32_t*)(gv + ((long)(b * 8 + hB) * DIMH + dB) * S_ + col) =
                    f2h2(acc[mt][nt][2], acc[mt][nt][3]);
            }
        }
    }
}

// ---------------------------------------------------------------------------
// Tensor-core flash attention, split-KV (unchanged from R7/R8 pass).
// ---------------------------------------------------------------------------
#define KS_STRIDE 72     // halves per K/Q smem row
#define VS_STRIDE 136    // halves per V smem row

__global__ __launch_bounds__(128)
void attn_f16(const __half* __restrict__ q16, const __half* __restrict__ k16,
              const __half* __restrict__ v16, float* __restrict__ opart,
              float* __restrict__ ml)
{
    __shared__ __half Qs[T_ * KS_STRIDE];       // 64 x 72
    __shared__ __half Ks[128 * KS_STRIDE];      // 128 x 72
    __shared__ __half Vs[DIMH * VS_STRIDE];     // 64 x 136

    const int sp  = blockIdx.x;
    const int bh  = blockIdx.y;
    const int tid = threadIdx.x;
    const int warp = tid >> 5;
    const int lane = tid & 31;
    const int g   = lane >> 2;
    const int tg  = lane & 3;
    const int wm  = warp * 16;

    // stage Q (64 x 64 halves)
    const __half* qb = q16 + (long)bh * T_ * DIMH;
    #pragma unroll
    for (int t = 0; t < 4; t++) {
        const int idx = tid + t * 128;
        const int r = idx >> 3, c8 = idx & 7;
        *(uint4*)&Qs[r * KS_STRIDE + c8 * 8] = *(const uint4*)&qb[r * DIMH + c8 * 8];
    }
    __syncthreads();

    // Q fragments: 4 k-steps over d
    uint32_t aq[4][4];
    #pragma unroll
    for (int ks = 0; ks < 4; ks++) {
        aq[ks][0] = *(const uint32_t*)&Qs[(wm + g)     * KS_STRIDE + ks * 16 + 2 * tg];
        aq[ks][1] = *(const uint32_t*)&Qs[(wm + g + 8) * KS_STRIDE + ks * 16 + 2 * tg];
        aq[ks][2] = *(const uint32_t*)&Qs[(wm + g)     * KS_STRIDE + ks * 16 + 2 * tg + 8];
        aq[ks][3] = *(const uint32_t*)&Qs[(wm + g + 8) * KS_STRIDE + ks * 16 + 2 * tg + 8];
    }

    float accO[8][4];
    #pragma unroll
    for (int nt = 0; nt < 8; nt++)
        #pragma unroll
        for (int i = 0; i < 4; i++) accO[nt][i] = 0.f;
    float m0r = -1e30f, m1r = -1e30f, l0 = 0.f, l1 = 0.f;

    const __half* kb = k16 + ((long)bh * S_ + sp * S_PER) * DIMH;
    const __half* vb = v16 + (long)bh * DIMH * S_ + sp * S_PER;

    for (int tile = 0; tile < S_PER / 128; tile++) {
        __syncthreads();
        #pragma unroll
        for (int t = 0; t < 8; t++) {            // K: 128 x 64 halves
            const int idx = tid + t * 128;
            const int r = idx >> 3, c8 = idx & 7;
            *(uint4*)&Ks[r * KS_STRIDE + c8 * 8] =
                *(const uint4*)&kb[(long)(tile * 128 + r) * DIMH + c8 * 8];
        }
        #pragma unroll
        for (int t = 0; t < 8; t++) {            // V: 64 x 128 halves
            const int idx = tid + t * 128;
            const int r = idx >> 4, c16 = idx & 15;
            *(uint4*)&Vs[r * VS_STRIDE + c16 * 8] =
                *(const uint4*)&vb[(long)r * S_ + tile * 128 + c16 * 8];
        }
        __syncthreads();

        // QK^T
        float accS[16][4];
        #pragma unroll
        for (int nt = 0; nt < 16; nt++)
            #pragma unroll
            for (int i = 0; i < 4; i++) accS[nt][i] = 0.f;

        #pragma unroll
        for (int ks = 0; ks < 4; ks++) {
            #pragma unroll
            for (int nt = 0; nt < 16; nt++) {
                uint32_t b0 = *(const uint32_t*)&Ks[(nt * 8 + g) * KS_STRIDE + ks * 16 + 2 * tg];
                uint32_t b1 = *(const uint32_t*)&Ks[(nt * 8 + g) * KS_STRIDE + ks * 16 + 2 * tg + 8];
                asm volatile(
                    "mma.sync.aligned.m16n8k16.row.col.f32.f16.f16.f32 "
                    "{%0,%1,%2,%3}, {%4,%5,%6,%7}, {%8,%9}, {%0,%1,%2,%3};"
                    : "+f"(accS[nt][0]), "+f"(accS[nt][1]),
                      "+f"(accS[nt][2]), "+f"(accS[nt][3])
                    : "r"(aq[ks][0]), "r"(aq[ks][1]), "r"(aq[ks][2]), "r"(aq[ks][3]),
                      "r"(b0), "r"(b1));
            }
        }

        // online softmax (rows g and g+8)
        float mx0 = -1e30f, mx1 = -1e30f;
        #pragma unroll
        for (int nt = 0; nt < 16; nt++) {
            mx0 = fmaxf(mx0, fmaxf(accS[nt][0], accS[nt][1]));
            mx1 = fmaxf(mx1, fmaxf(accS[nt][2], accS[nt][3]));
        }
        mx0 = fmaxf(mx0, __shfl_xor_sync(0xffffffffu, mx0, 1));
        mx0 = fmaxf(mx0, __shfl_xor_sync(0xffffffffu, mx0, 2));
        mx1 = fmaxf(mx1, __shfl_xor_sync(0xffffffffu, mx1, 1));
        mx1 = fmaxf(mx1, __shfl_xor_sync(0xffffffffu, mx1, 2));

        const float mn0 = fmaxf(m0r, mx0);
        const float mn1 = fmaxf(m1r, mx1);
        const float cr0 = __expf(m0r - mn0);
        const float cr1 = __expf(m1r - mn1);
        m0r = mn0; m1r = mn1;

        float s0 = 0.f, s1 = 0.f;
        #pragma unroll
        for (int nt = 0; nt < 16; nt++) {
            accS[nt][0] = __expf(accS[nt][0] - mn0);
            accS[nt][1] = __expf(accS[nt][1] - mn0);
            accS[nt][2] = __expf(accS[nt][2] - mn1);
            accS[nt][3] = __expf(accS[nt][3] - mn1);
            s0 += accS[nt][0] + accS[nt][1];
            s1 += accS[nt][2] + accS[nt][3];
        }
        s0 += __shfl_xor_sync(0xffffffffu, s0, 1);
        s0 += __shfl_xor_sync(0xffffffffu, s0, 2);
        s1 += __shfl_xor_sync(0xffffffffu, s1, 1);
        s1 += __shfl_xor_sync(0xffffffffu, s1, 2);
        l0 = l0 * cr0 + s0;
        l1 = l1 * cr1 + s1;

        #pragma unroll
        for (int nt = 0; nt < 8; nt++) {
            accO[nt][0] *= cr0; accO[nt][1] *= cr0;
            accO[nt][2] *= cr1; accO[nt][3] *= cr1;
        }

        // P -> half2 A-fragments
        uint32_t ap[8][4];
        #pragma unroll
        for (int ks = 0; ks < 8; ks++) {
            ap[ks][0] = f2h2(accS[2*ks][0],   accS[2*ks][1]);
            ap[ks][1] = f2h2(accS[2*ks][2],   accS[2*ks][3]);
            ap[ks][2] = f2h2(accS[2*ks+1][0], accS[2*ks+1][1]);
            ap[ks][3] = f2h2(accS[2*ks+1][2], accS[2*ks+1][3]);
        }

        // P @ V
        #pragma unroll
        for (int ks = 0; ks < 8; ks++) {
            #pragma unroll
            for (int nt = 0; nt < 8; nt++) {
                uint32_t b0 = *(const uint32_t*)&Vs[(nt * 8 + g) * VS_STRIDE + ks * 16 + 2 * tg];
                uint32_t b1 = *(const uint32_t*)&Vs[(nt * 8 + g) * VS_STRIDE + ks * 16 + 2 * tg + 8];
                asm volatile(
                    "mma.sync.aligned.m16n8k16.row.col.f32.f16.f16.f32 "
                    "{%0,%1,%2,%3}, {%4,%5,%6,%7}, {%8,%9}, {%0,%1,%2,%3};"
                    : "+f"(accO[nt][0]), "+f"(accO[nt][1]),
                      "+f"(accO[nt][2]), "+f"(accO[nt][3])
                    : "r"(ap[ks][0]), "r"(ap[ks][1]), "r"(ap[ks][2]), "r"(ap[ks][3]),
                      "r"(b0), "r"(b1));
            }
        }
    }

    // write partials (unnormalized) + (m, l)
    float* op = opart + ((long)(sp * BH_ + bh) * T_) * DIMH;
    const int rA = wm + g, rB = wm + g + 8;
    #pragma unroll
    for (int nt = 0; nt < 8; nt++) {
        const int col = nt * 8 + 2 * tg;
        *(float2*)&op[rA * DIMH + col] = make_float2(accO[nt][0], accO[nt][1]);
        *(float2*)&op[rB * DIMH + col] = make_float2(accO[nt][2], accO[nt][3]);
    }
    if (tg == 0) {
        float* mlp = ml + ((long)(sp * BH_ + bh) * T_) * 2;
        mlp[rA * 2] = m0r; mlp[rA * 2 + 1] = l0;
        mlp[rB * 2] = m1r; mlp[rB * 2 + 1] = l1;
    }
}

// ---------------------------------------------------------------------------
// split-KV combine -> g_ao (B,T,inner) f32   [validated in R8]
// ---------------------------------------------------------------------------
__global__ void attn_combine(const float* __restrict__ opart,
                             const float* __restrict__ ml, float* __restrict__ ao)
{
    const int bh  = blockIdx.x;
    const int b   = bh >> 3;
    const int h   = bh & 7;
    const int tid = threadIdx.x;       // 128
    const int t   = tid >> 1;
    const int d0  = (tid & 1) * 32;

    float m[SPLIT], l[SPLIT];
    float M = -1e30f;
    #pragma unroll
    for (int i = 0; i < SPLIT; i++) {
        m[i] = ml[((long)(i * BH_ + bh) * T_ + t) * 2];
        l[i] = ml[((long)(i * BH_ + bh) * T_ + t) * 2 + 1];
        M = fmaxf(M, m[i]);
    }
    float w[SPLIT], L = 0.f;
    #pragma unroll
    for (int i = 0; i < SPLIT; i++) {
        w[i] = __expf(m[i] - M);
        L += w[i] * l[i];
    }
    const float inv = 1.f / L;

    float* dst = ao + ((long)(b * T_ + t)) * INNER + h * DIMH + d0;
    #pragma unroll
    for (int d = 0; d < 32; d++) {
        float o = 0.f;
        #pragma unroll
        for (int i = 0; i < SPLIT; i++)
            o += w[i] * opart[((long)(i * BH_ + bh) * T_ + t) * DIMH + d0 + d];
        dst[d] = o * inv;
    }
}

// ---------------------------------------------------------------------------
extern "C" void kernel_launch(void* const* d_in, const int* in_sizes, int n_in,
                              void* d_out, int out_size)
{
    const float* vis  = (const float*)d_in[0];
    const float* lang = (const float*)d_in[1];
    // d_in[2] = mask (unused)
    const float* Wq   = (const float*)d_in[3];
    const float* Wk   = (const float*)d_in[4];
    const float* Wv   = (const float*)d_in[5];
    const float* Wo   = (const float*)d_in[6];
    float* out = (float*)d_out;

    float *q, *ao, *op, *ml;
    __half *w16, *lang16, *ao16, *q16, *k16, *v16;
    uint32_t *v16p, *wqT, *woT;
    cudaGetSymbolAddress((void**)&q,      g_q);
    cudaGetSymbolAddress((void**)&ao,     g_ao);
    cudaGetSymbolAddress((void**)&w16,    g_w16);
    cudaGetSymbolAddress((void**)&lang16, g_lang16);
    cudaGetSymbolAddress((void**)&ao16,   g_ao16);
    cudaGetSymbolAddress((void**)&wqT,    g_wqT);
    cudaGetSymbolAddress((void**)&woT,    g_woT);
    cudaGetSymbolAddress((void**)&v16p,   g_v16p);
    cudaGetSymbolAddress((void**)&q16,    g_q16);
    cudaGetSymbolAddress((void**)&k16,    g_k16);
    cudaGetSymbolAddress((void**)&v16,    g_v16);
    cudaGetSymbolAddress((void**)&op,     g_op);
    cudaGetSymbolAddress((void**)&ml,     g_ml);

    cudaFuncSetAttribute(gemm_kv_f16, cudaFuncAttributeMaxDynamicSharedMemorySize,
                         KV_SMEM);
    cudaFuncSetAttribute(gemm_proj, cudaFuncAttributeMaxDynamicSharedMemorySize,
                         KV_SMEM);

    // prep conversions / packs
    prep_w16<<<INNER * C_ / 256, 256>>>(Wk, Wv, w16);
    prep_vis16<<<(int)(((long)B_ * (C_ / 2) * S_) / 256), 256>>>(vis, v16p);
    conv16<<<B_ * T_ * C_ / 256, 256>>>(lang, lang16);
    packT<<<(C_ / 2) * INNER / 256, 256>>>(Wq, wqT);
    packT<<<(INNER / 2) * C_ / 256, 256>>>(Wo, woT);

    // q projection (fp16 mma) -> f32 q, then validated repack to q16
    gemm_proj<<<dim3(INNER / 128, (B_ * T_) / 128), 256, KV_SMEM>>>(lang16, wqT, q);
    prep_q16<<<B_ * T_ * INNER / 256, 256>>>(q, q16);

    // fused k+v projection (fp16 tensor cores, cp.async pipeline)
    gemm_kv_f16<<<dim3(S_ / 128, (2 * INNER) / 128, B_), 256, KV_SMEM>>>(w16, v16p, k16, v16);

    // flash attention (tensor cores, split-KV) + combine (f32), then fp16 repack
    attn_f16<<<dim3(SPLIT, BH_), 128>>>(q16, k16, v16, op, ml);
    attn_combine<<<BH_, 128>>>(op, ml, ao);
    conv16<<<B_ * T_ * INNER / 256, 256>>>(ao, ao16);

    // output projection (fp16 mma) -> f32 out
    gemm_proj<<<dim3(C_ / 128, (B_ * T_) / 128), 256, KV_SMEM>>>(ao16, woT, out);
}

// round 11
// speedup vs baseline: 9.0625x; 1.0423x over previous
#include <cuda_runtime.h>
#include <cuda_fp16.h>
#include <cstdint>

// Problem constants
#define B_    16
#define T_    64
#define C_    512
#define S_    4096
#define INNER 512
#define DIMH  64
#define NHEAD 8
#define BH_   (B_ * NHEAD)
#define SPLIT 4
#define S_PER (S_ / SPLIT)      // 1024

// Scratch (device globals; no allocations allowed)
__device__ float    g_q    [B_ * T_ * INNER];             // q projection f32
__device__ float    g_ao   [B_ * T_ * INNER];             // attention out f32
__device__ __half   g_w16  [2 * INNER * C_];              // concat(Wk,Wv) fp16
__device__ __half   g_lang16[B_ * T_ * C_];               // lang fp16 [1024][512]
__device__ __half   g_ao16 [B_ * T_ * INNER];             // attention out fp16
__device__ uint32_t g_wqT  [(C_ / 2) * INNER];            // Wq^T pair-packed [256][512]
__device__ uint32_t g_woT  [(INNER / 2) * C_];            // Wo^T pair-packed [256][512]
__device__ uint32_t g_v16p [(long)B_ * (C_ / 2) * S_];    // vis fp16 pair-packed
__device__ __half   g_q16  [BH_ * T_ * DIMH];             // q fp16 (bh,t,d), pre-scaled
__device__ __half   g_k16  [(long)BH_ * S_ * DIMH];       // K fp16 s-major (bh,s,d)
__device__ __half   g_v16  [(long)BH_ * DIMH * S_];       // V fp16 d-major (bh,d,s)
__device__ float    g_op   [(long)SPLIT * BH_ * T_ * DIMH]; // partial O
__device__ float    g_ml   [SPLIT * BH_ * T_ * 2];        // partial (m,l)

// pack two fp32 -> one .f16x2 register (lo = first arg)
__device__ __forceinline__ uint32_t f2h2(float lo, float hi) {
    uint32_t r;
    asm("cvt.rn.f16x2.f32 %0, %1, %2;" : "=r"(r) : "f"(hi), "f"(lo));
    return r;
}

__device__ __forceinline__ uint32_t smem_u32(const void* p) {
    uint32_t a;
    asm("{ .reg .u64 t; cvta.to.shared.u64 t, %1; cvt.u32.u64 %0, t; }" : "=r"(a) : "l"(p));
    return a;
}

// ---------------------------------------------------------------------------
__global__ void conv16(const float* __restrict__ src, __half* __restrict__ dst)
{
    const int i = blockIdx.x * 256 + threadIdx.x;
    dst[i] = __float2half_rn(src[i]);
}

// fused prep: w16 concat (blocks 0..1023), Wq^T pack (1024..1535),
// Wo^T pack (1536..2047), lang conv (2048..4095)
__global__ void prep_all(const float* __restrict__ Wk, const float* __restrict__ Wv,
                         const float* __restrict__ Wq, const float* __restrict__ Wo,
                         const float* __restrict__ lang,
                         __half* __restrict__ w16, uint32_t* __restrict__ wqT,
                         uint32_t* __restrict__ woT, __half* __restrict__ lang16)
{
    const int blk = blockIdx.x;
    if (blk < 1024) {
        const int i = blk * 256 + threadIdx.x;
        w16[i]              = __float2half_rn(Wk[i]);
        w16[INNER * C_ + i] = __float2half_rn(Wv[i]);
    } else if (blk < 1536) {
        const int idx = (blk - 1024) * 256 + threadIdx.x;   // k2*512 + n
        const int n  = idx & 511;
        const int k2 = idx >> 9;
        const float* s = Wq + n * 512 + 2 * k2;
        wqT[idx] = f2h2(s[0], s[1]);
    } else if (blk < 2048) {
        const int idx = (blk - 1536) * 256 + threadIdx.x;
        const int n  = idx & 511;
        const int k2 = idx >> 9;
        const float* s = Wo + n * 512 + 2 * k2;
        woT[idx] = f2h2(s[0], s[1]);
    } else {
        const int i = (blk - 2048) * 256 + threadIdx.x;
        lang16[i] = __float2half_rn(lang[i]);
    }
}

__global__ void prep_vis16(const float* __restrict__ vis, uint32_t* __restrict__ vp)
{
    const long i  = (long)blockIdx.x * 256 + threadIdx.x;
    const long s  = i & (S_ - 1);
    const long c2 = (i >> 12) & 255;
    const long b  = i >> 20;
    const float* src = vis + (((b * C_) + 2 * c2) << 12) + s;
    vp[i] = f2h2(src[0], src[S_]);
}

// q f32 (B,T,inner) -> q16 (bh,t,d), scaled by 0.125   [validated]
__global__ void prep_q16(const float* __restrict__ q, __half* __restrict__ q16)
{
    const int i = blockIdx.x * 256 + threadIdx.x;   // 0 .. 524287
    const int d = i & 63;
    const int h = (i >> 6) & 7;
    const int t = (i >> 9) & 63;
    const int b = i >> 15;
    q16[(((b * 8 + h) * T_) + t) * DIMH + d] = __float2half_rn(q[i] * 0.125f);
}

// ---------------------------------------------------------------------------
// shared tile sizes (kv kernel + its clone)
#define NSTAGE   4
#define A_ST_U32 (128 * 20)
#define B_ST_U32 (16 * 136)
#define KV_SMEM  (NSTAGE * (A_ST_U32 + B_ST_U32) * 4)   // 75776 bytes

// ---------------------------------------------------------------------------
// Projection GEMM: Cf[1024][512] = A16[1024][512] @ (packed B)[512][512]
// Verbatim clone of gemm_kv_f16 mainloop with N=512 and f32 epilogue.  [validated]
// ---------------------------------------------------------------------------
__global__ __launch_bounds__(256)
void gemm_proj(const __half* __restrict__ A16,      // [1024][512]
               const uint32_t* __restrict__ Bp,     // [256][512] pairs k2-major
               float* __restrict__ Cf)              // [1024][512]
{
    extern __shared__ uint32_t smdyn[];
    uint32_t (*As)[128][20]  = (uint32_t(*)[128][20])smdyn;
    uint32_t (*Bs)[16][136]  = (uint32_t(*)[16][136])(smdyn + NSTAGE * A_ST_U32);

    const int m0 = blockIdx.y * 128;
    const int n0 = blockIdx.x * 128;
    const uint32_t* Ap = (const uint32_t*)A16;               // pair view [1024][256]

    const int tid  = threadIdx.x;
    const int warp = tid >> 5;
    const int lane = tid & 31;
    const int wm   = (warp >> 1) * 32;
    const int wn   = (warp & 1) * 64;
    const int g    = lane >> 2;
    const int tg   = lane & 3;

    float acc[2][8][4];
    #pragma unroll
    for (int mt = 0; mt < 2; mt++)
        #pragma unroll
        for (int nt = 0; nt < 8; nt++)
            #pragma unroll
            for (int i = 0; i < 4; i++)
                acc[mt][nt][i] = 0.f;

    auto issue = [&](int ch, int st) {
        const int kc2 = ch * 16;
        #pragma unroll
        for (int t = 0; t < 2; t++) {
            const int idx = tid + t * 256;
            const int r = idx >> 2, p4 = (idx & 3) * 4;
            const uint32_t* src = &Ap[(long)(m0 + r) * (C_ / 2) + kc2 + p4];
            asm volatile("cp.async.cg.shared.global [%0], [%1], 16;"
                         :: "r"(smem_u32(&As[st][r][p4])), "l"(src));
        }
        #pragma unroll
        for (int t = 0; t < 2; t++) {
            const int idx = tid + t * 256;
            const int r = idx >> 5, c4 = (idx & 31) * 4;
            const uint32_t* src = &Bp[(long)(kc2 + r) * 512 + n0 + c4];
            asm volatile("cp.async.cg.shared.global [%0], [%1], 16;"
                         :: "r"(smem_u32(&Bs[st][r][c4])), "l"(src));
        }
        asm volatile("cp.async.commit_group;" ::: "memory");
    };

    issue(0, 0); issue(1, 1); issue(2, 2);

    const int NCH = C_ / 32;   // 16
    for (int ch = 0; ch < NCH; ++ch) {
        const int st = ch & (NSTAGE - 1);
        asm volatile("cp.async.wait_group 2;" ::: "memory");
        __syncthreads();

        #pragma unroll
        for (int ks = 0; ks < 2; ks++) {
            const int kb = ks * 8;
            uint32_t bf[8][2];
            #pragma unroll
            for (int nt = 0; nt < 8; nt++) {
                bf[nt][0] = Bs[st][kb + tg]    [wn + nt * 8 + g];
                bf[nt][1] = Bs[st][kb + tg + 4][wn + nt * 8 + g];
            }
            #pragma unroll
            for (int mt = 0; mt < 2; mt++) {
                const int mi = wm + mt * 16 + g;
                uint32_t a0 = As[st][mi]    [kb + tg];
                uint32_t a1 = As[st][mi + 8][kb + tg];
                uint32_t a2 = As[st][mi]    [kb + tg + 4];
                uint32_t a3 = As[st][mi + 8][kb + tg + 4];
                #pragma unroll
                for (int nt = 0; nt < 8; nt++) {
                    asm volatile(
                        "mma.sync.aligned.m16n8k16.row.col.f32.f16.f16.f32 "
                        "{%0,%1,%2,%3}, {%4,%5,%6,%7}, {%8,%9}, {%0,%1,%2,%3};"
                        : "+f"(acc[mt][nt][0]), "+f"(acc[mt][nt][1]),
                          "+f"(acc[mt][nt][2]), "+f"(acc[mt][nt][3])
                        : "r"(a0), "r"(a1), "r"(a2), "r"(a3),
                          "r"(bf[nt][0]), "r"(bf[nt][1]));
                }
            }
        }

        if (ch + NSTAGE - 1 < NCH)
            issue(ch + NSTAGE - 1, (ch + NSTAGE - 1) & (NSTAGE - 1));
    }

    #pragma unroll
    for (int mt = 0; mt < 2; mt++) {
        const int rA = m0 + wm + mt * 16 + g;
        const int rB = rA + 8;
        #pragma unroll
        for (int nt = 0; nt < 8; nt++) {
            const int col = n0 + wn + nt * 8 + 2 * tg;
            *(float2*)&Cf[(long)rA * 512 + col] = make_float2(acc[mt][nt][0], acc[mt][nt][1]);
            *(float2*)&Cf[(long)rB * 512 + col] = make_float2(acc[mt][nt][2], acc[mt][nt][3]);
        }
    }
}

// ---------------------------------------------------------------------------
// Fused k/v projection, fp16 mma, 4-stage cp.async (unchanged).  [validated]
// ---------------------------------------------------------------------------
__global__ __launch_bounds__(256)
void gemm_kv_f16(const __half* __restrict__ A16,      // [1024][512]
                 const uint32_t* __restrict__ Bp,     // [16][256][4096] pairs
                 __half* __restrict__ gk,             // (bh,s,d)
                 __half* __restrict__ gv)             // (bh,d,s)
{
    extern __shared__ uint32_t smdyn[];
    uint32_t (*As)[128][20]  = (uint32_t(*)[128][20])smdyn;
    uint32_t (*Bs)[16][136]  = (uint32_t(*)[16][136])(smdyn + NSTAGE * A_ST_U32);

    const int b  = blockIdx.z;
    const int m0 = blockIdx.y * 128;
    const int n0 = blockIdx.x * 128;
    const uint32_t* Ap = (const uint32_t*)A16;
    const uint32_t* Bb = Bp + (long)b * (C_ / 2) * S_;

    const int tid  = threadIdx.x;
    const int warp = tid >> 5;
    const int lane = tid & 31;
    const int wm   = (warp >> 1) * 32;
    const int wn   = (warp & 1) * 64;
    const int g    = lane >> 2;
    const int tg   = lane & 3;

    float acc[2][8][4];
    #pragma unroll
    for (int mt = 0; mt < 2; mt++)
        #pragma unroll
        for (int nt = 0; nt < 8; nt++)
            #pragma unroll
            for (int i = 0; i < 4; i++)
                acc[mt][nt][i] = 0.f;

    auto issue = [&](int ch, int st) {
        const int kc2 = ch * 16;
        #pragma unroll
        for (int t = 0; t < 2; t++) {
            const int idx = tid + t * 256;
            const int r = idx >> 2, p4 = (idx & 3) * 4;
            const uint32_t* src = &Ap[(long)(m0 + r) * (C_ / 2) + kc2 + p4];
            asm volatile("cp.async.cg.shared.global [%0], [%1], 16;"
                         :: "r"(smem_u32(&As[st][r][p4])), "l"(src));
        }
        #pragma unroll
        for (int t = 0; t < 2; t++) {
            const int idx = tid + t * 256;
            const int r = idx >> 5, c4 = (idx & 31) * 4;
            const uint32_t* src = &Bb[(long)(kc2 + r) * S_ + n0 + c4];
            asm volatile("cp.async.cg.shared.global [%0], [%1], 16;"
                         :: "r"(smem_u32(&Bs[st][r][c4])), "l"(src));
        }
        asm volatile("cp.async.commit_group;" ::: "memory");
    };

    issue(0, 0); issue(1, 1); issue(2, 2);

    const int NCH = C_ / 32;   // 16
    for (int ch = 0; ch < NCH; ++ch) {
        const int st = ch & (NSTAGE - 1);
        asm volatile("cp.async.wait_group 2;" ::: "memory");
        __syncthreads();

        #pragma unroll
        for (int ks = 0; ks < 2; ks++) {
            const int kb = ks * 8;
            uint32_t bf[8][2];
            #pragma unroll
            for (int nt = 0; nt < 8; nt++) {
                bf[nt][0] = Bs[st][kb + tg]    [wn + nt * 8 + g];
                bf[nt][1] = Bs[st][kb + tg + 4][wn + nt * 8 + g];
            }
            #pragma unroll
            for (int mt = 0; mt < 2; mt++) {
                const int mi = wm + mt * 16 + g;
                uint32_t a0 = As[st][mi]    [kb + tg];
                uint32_t a1 = As[st][mi + 8][kb + tg];
                uint32_t a2 = As[st][mi]    [kb + tg + 4];
                uint32_t a3 = As[st][mi + 8][kb + tg + 4];
                #pragma unroll
                for (int nt = 0; nt < 8; nt++) {
                    asm volatile(
                        "mma.sync.aligned.m16n8k16.row.col.f32.f16.f16.f32 "
                        "{%0,%1,%2,%3}, {%4,%5,%6,%7}, {%8,%9}, {%0,%1,%2,%3};"
                        : "+f"(acc[mt][nt][0]), "+f"(acc[mt][nt][1]),
                          "+f"(acc[mt][nt][2]), "+f"(acc[mt][nt][3])
                        : "r"(a0), "r"(a1), "r"(a2), "r"(a3),
                          "r"(bf[nt][0]), "r"(bf[nt][1]));
                }
            }
        }

        if (ch + NSTAGE - 1 < NCH)
            issue(ch + NSTAGE - 1, (ch + NSTAGE - 1) & (NSTAGE - 1));
    }

    // epilogue: K rows (m<512) -> (bh,s,d) scalar halves; V rows -> (bh,d,s) half2
    #pragma unroll
    for (int mt = 0; mt < 2; mt++) {
        const int mA = m0 + wm + mt * 16 + g;
        const int mB = mA + 8;
        #pragma unroll
        for (int nt = 0; nt < 8; nt++) {
            const int col = n0 + wn + nt * 8 + 2 * tg;
            if (m0 < 512) {
                const int hA = mA >> 6, dA = mA & 63;
                const int hB = mB >> 6, dB = mB & 63;
                __half* pA = gk + ((long)(b * 8 + hA) * S_ + col) * DIMH + dA;
                __half* pB = gk + ((long)(b * 8 + hB) * S_ + col) * DIMH + dB;
                pA[0]    = __float2half_rn(acc[mt][nt][0]);
                pA[DIMH] = __float2half_rn(acc[mt][nt][1]);
                pB[0]    = __float2half_rn(acc[mt][nt][2]);
                pB[DIMH] = __float2half_rn(acc[mt][nt][3]);
            } else {
                const int m2A = mA - 512, m2B = mB - 512;
                const int hA = m2A >> 6, dA = m2A & 63;
                const int hB = m2B >> 6, dB = m2B & 63;
                *(uint32_t*)(gv + ((long)(b * 8 + hA) * DIMH + dA) * S_ + col) =
                    f2h2(acc[mt][nt][0], acc[mt][nt][1]);
                *(uint32_t*)(gv + ((long)(b * 8 + hB) * DIMH + dB) * S_ + col) =
                    f2h2(acc[mt][nt][2], acc[mt][nt][3]);
            }
        }
    }
}

// ---------------------------------------------------------------------------
// Tensor-core flash attention, split-KV, double-buffered cp.async K/V staging.
// Compute body identical to the validated R7/R8/R10 kernel; only the staging
// mechanism changed (sync LDG/STS -> cp.async ring of 2).
// ---------------------------------------------------------------------------
#define KS_STRIDE 72     // halves per K/Q smem row
#define VS_STRIDE 136    // halves per V smem row
#define QS_HALVES (T_ * KS_STRIDE)          // 4608
#define KS_HALVES (128 * KS_STRIDE)         // 9216
#define VS_HALVES (DIMH * VS_STRIDE)        // 8704
#define ATTN_SMEM ((QS_HALVES + 2 * KS_HALVES + 2 * VS_HALVES) * 2)   // 80896 B

__global__ __launch_bounds__(128)
void attn_f16(const __half* __restrict__ q16, const __half* __restrict__ k16,
              const __half* __restrict__ v16, float* __restrict__ opart,
              float* __restrict__ ml)
{
    extern __shared__ __half smd[];
    __half* Qs  = smd;
    __half* Ksb = smd + QS_HALVES;                  // 2 x KS_HALVES
    __half* Vsb = smd + QS_HALVES + 2 * KS_HALVES;  // 2 x VS_HALVES

    const int sp  = blockIdx.x;
    const int bh  = blockIdx.y;
    const int tid = threadIdx.x;
    const int warp = tid >> 5;
    const int lane = tid & 31;
    const int g   = lane >> 2;
    const int tg  = lane & 3;
    const int wm  = warp * 16;

    const __half* kb = k16 + ((long)bh * S_ + sp * S_PER) * DIMH;
    const __half* vb = v16 + (long)bh * DIMH * S_ + sp * S_PER;
    const int NT = S_PER / 128;   // 8

    // async tile loader (same addresses as the validated sync loops)
    auto issue_tile = [&](int tile, int buf) {
        __half* Ks = Ksb + buf * KS_HALVES;
        __half* Vs = Vsb + buf * VS_HALVES;
        #pragma unroll
        for (int t = 0; t < 8; t++) {            // K: 128 x 64 halves
            const int idx = tid + t * 128;
            const int r = idx >> 3, c8 = idx & 7;
            const __half* src = &kb[(long)(tile * 128 + r) * DIMH + c8 * 8];
            asm volatile("cp.async.cg.shared.global [%0], [%1], 16;"
                         :: "r"(smem_u32(&Ks[r * KS_STRIDE + c8 * 8])), "l"(src));
        }
        #pragma unroll
        for (int t = 0; t < 8; t++) {            // V: 64 x 128 halves
            const int idx = tid + t * 128;
            const int r = idx >> 4, c16 = idx & 15;
            const __half* src = &vb[(long)r * S_ + tile * 128 + c16 * 8];
            asm volatile("cp.async.cg.shared.global [%0], [%1], 16;"
                         :: "r"(smem_u32(&Vs[r * VS_STRIDE + c16 * 8])), "l"(src));
        }
        asm volatile("cp.async.commit_group;" ::: "memory");
    };

    issue_tile(0, 0);
    issue_tile(1, 1);

    // stage Q (64 x 64 halves) while the first tiles are in flight
    const __half* qb = q16 + (long)bh * T_ * DIMH;
    #pragma unroll
    for (int t = 0; t < 4; t++) {
        const int idx = tid + t * 128;
        const int r = idx >> 3, c8 = idx & 7;
        *(uint4*)&Qs[r * KS_STRIDE + c8 * 8] = *(const uint4*)&qb[r * DIMH + c8 * 8];
    }
    __syncthreads();

    // Q fragments: 4 k-steps over d
    uint32_t aq[4][4];
    #pragma unroll
    for (int ks = 0; ks < 4; ks++) {
        aq[ks][0] = *(const uint32_t*)&Qs[(wm + g)     * KS_STRIDE + ks * 16 + 2 * tg];
        aq[ks][1] = *(const uint32_t*)&Qs[(wm + g + 8) * KS_STRIDE + ks * 16 + 2 * tg];
        aq[ks][2] = *(const uint32_t*)&Qs[(wm + g)     * KS_STRIDE + ks * 16 + 2 * tg + 8];
        aq[ks][3] = *(const uint32_t*)&Qs[(wm + g + 8) * KS_STRIDE + ks * 16 + 2 * tg + 8];
    }

    float accO[8][4];
    #pragma unroll
    for (int nt = 0; nt < 8; nt++)
        #pragma unroll
        for (int i = 0; i < 4; i++) accO[nt][i] = 0.f;
    float m0r = -1e30f, m1r = -1e30f, l0 = 0.f, l1 = 0.f;

    for (int tile = 0; tile < NT; tile++) {
        const int buf = tile & 1;
        __half* Ks = Ksb + buf * KS_HALVES;
        __half* Vs = Vsb + buf * VS_HALVES;

        if (tile + 1 < NT)
            asm volatile("cp.async.wait_group 1;" ::: "memory");
        else
            asm volatile("cp.async.wait_group 0;" ::: "memory");
        __syncthreads();

        // QK^T
        float accS[16][4];
        #pragma unroll
        for (int nt = 0; nt < 16; nt++)
            #pragma unroll
            for (int i = 0; i < 4; i++) accS[nt][i] = 0.f;

        #pragma unroll
        for (int ks = 0; ks < 4; ks++) {
            #pragma unroll
            for (int nt = 0; nt < 16; nt++) {
                uint32_t b0 = *(const uint32_t*)&Ks[(nt * 8 + g) * KS_STRIDE + ks * 16 + 2 * tg];
                uint32_t b1 = *(const uint32_t*)&Ks[(nt * 8 + g) * KS_STRIDE + ks * 16 + 2 * tg + 8];
                asm volatile(
                    "mma.sync.aligned.m16n8k16.row.col.f32.f16.f16.f32 "
                    "{%0,%1,%2,%3}, {%4,%5,%6,%7}, {%8,%9}, {%0,%1,%2,%3};"
                    : "+f"(accS[nt][0]), "+f"(accS[nt][1]),
                      "+f"(accS[nt][2]), "+f"(accS[nt][3])
                    : "r"(aq[ks][0]), "r"(aq[ks][1]), "r"(aq[ks][2]), "r"(aq[ks][3]),
                      "r"(b0), "r"(b1));
            }
        }

        // online softmax (rows g and g+8)
        float mx0 = -1e30f, mx1 = -1e30f;
        #pragma unroll
        for (int nt = 0; nt < 16; nt++) {
            mx0 = fmaxf(mx0, fmaxf(accS[nt][0], accS[nt][1]));
            mx1 = fmaxf(mx1, fmaxf(accS[nt][2], accS[nt][3]));
        }
        mx0 = fmaxf(mx0, __shfl_xor_sync(0xffffffffu, mx0, 1));
        mx0 = fmaxf(mx0, __shfl_xor_sync(0xffffffffu, mx0, 2));
        mx1 = fmaxf(mx1, __shfl_xor_sync(0xffffffffu, mx1, 1));
        mx1 = fmaxf(mx1, __shfl_xor_sync(0xffffffffu, mx1, 2));

        const float mn0 = fmaxf(m0r, mx0);
        const float mn1 = fmaxf(m1r, mx1);
        const float cr0 = __expf(m0r - mn0);
        const float cr1 = __expf(m1r - mn1);
        m0r = mn0; m1r = mn1;

        float s0 = 0.f, s1 = 0.f;
        #pragma unroll
        for (int nt = 0; nt < 16; nt++) {
            accS[nt][0] = __expf(accS[nt][0] - mn0);
            accS[nt][1] = __expf(accS[nt][1] - mn0);
            accS[nt][2] = __expf(accS[nt][2] - mn1);
            accS[nt][3] = __expf(accS[nt][3] - mn1);
            s0 += accS[nt][0] + accS[nt][1];
            s1 += accS[nt][2] + accS[nt][3];
        }
        s0 += __shfl_xor_sync(0xffffffffu, s0, 1);
        s0 += __shfl_xor_sync(0xffffffffu, s0, 2);
        s1 += __shfl_xor_sync(0xffffffffu, s1, 1);
        s1 += __shfl_xor_sync(0xffffffffu, s1, 2);
        l0 = l0 * cr0 + s0;
        l1 = l1 * cr1 + s1;

        #pragma unroll
        for (int nt = 0; nt < 8; nt++) {
            accO[nt][0] *= cr0; accO[nt][1] *= cr0;
            accO[nt][2] *= cr1; accO[nt][3] *= cr1;
        }

        // P -> half2 A-fragments
        uint32_t ap[8][4];
        #pragma unroll
        for (int ks = 0; ks < 8; ks++) {
            ap[ks][0] = f2h2(accS[2*ks][0],   accS[2*ks][1]);
            ap[ks][1] = f2h2(accS[2*ks][2],   accS[2*ks][3]);
            ap[ks][2] = f2h2(accS[2*ks+1][0], accS[2*ks+1][1]);
            ap[ks][3] = f2h2(accS[2*ks+1][2], accS[2*ks+1][3]);
        }

        // P @ V
        #pragma unroll
        for (int ks = 0; ks < 8; ks++) {
            #pragma unroll
            for (int nt = 0; nt < 8; nt++) {
                uint32_t b0 = *(const uint32_t*)&Vs[(nt * 8 + g) * VS_STRIDE + ks * 16 + 2 * tg];
                uint32_t b1 = *(const uint32_t*)&Vs[(nt * 8 + g) * VS_STRIDE + ks * 16 + 2 * tg + 8];
                asm volatile(
                    "mma.sync.aligned.m16n8k16.row.col.f32.f16.f16.f32 "
                    "{%0,%1,%2,%3}, {%4,%5,%6,%7}, {%8,%9}, {%0,%1,%2,%3};"
                    : "+f"(accO[nt][0]), "+f"(accO[nt][1]),
                      "+f"(accO[nt][2]), "+f"(accO[nt][3])
                    : "r"(ap[ks][0]), "r"(ap[ks][1]), "r"(ap[ks][2]), "r"(ap[ks][3]),
                      "r"(b0), "r"(b1));
            }
        }

        __syncthreads();   // all reads of buf done before it is refilled
        if (tile + 2 < NT)
            issue_tile(tile + 2, buf);
    }

    // write partials (unnormalized) + (m, l)
    float* op = opart + ((long)(sp * BH_ + bh) * T_) * DIMH;
    const int rA = wm + g, rB = wm + g + 8;
    #pragma unroll
    for (int nt = 0; nt < 8; nt++) {
        const int col = nt * 8 + 2 * tg;
        *(float2*)&op[rA * DIMH + col] = make_float2(accO[nt][0], accO[nt][1]);
        *(float2*)&op[rB * DIMH + col] = make_float2(accO[nt][2], accO[nt][3]);
    }
    if (tg == 0) {
        float* mlp = ml + ((long)(sp * BH_ + bh) * T_) * 2;
        mlp[rA * 2] = m0r; mlp[rA * 2 + 1] = l0;
        mlp[rB * 2] = m1r; mlp[rB * 2 + 1] = l1;
    }
}

// ---------------------------------------------------------------------------
// split-KV combine -> g_ao (B,T,inner) f32   [validated]
// ---------------------------------------------------------------------------
__global__ void attn_combine(const float* __restrict__ opart,
                             const float* __restrict__ ml, float* __restrict__ ao)
{
    const int bh  = blockIdx.x;
    const int b   = bh >> 3;
    const int h   = bh & 7;
    const int tid = threadIdx.x;       // 128
    const int t   = tid >> 1;
    const int d0  = (tid & 1) * 32;

    float m[SPLIT], l[SPLIT];
    float M = -1e30f;
    #pragma unroll
    for (int i = 0; i < SPLIT; i++) {
        m[i] = ml[((long)(i * BH_ + bh) * T_ + t) * 2];
        l[i] = ml[((long)(i * BH_ + bh) * T_ + t) * 2 + 1];
        M = fmaxf(M, m[i]);
    }
    float w[SPLIT], L = 0.f;
    #pragma unroll
    for (int i = 0; i < SPLIT; i++) {
        w[i] = __expf(m[i] - M);
        L += w[i] * l[i];
    }
    const float inv = 1.f / L;

    float* dst = ao + ((long)(b * T_ + t)) * INNER + h * DIMH + d0;
    #pragma unroll
    for (int d = 0; d < 32; d++) {
        float o = 0.f;
        #pragma unroll
        for (int i = 0; i < SPLIT; i++)
            o += w[i] * opart[((long)(i * BH_ + bh) * T_ + t) * DIMH + d0 + d];
        dst[d] = o * inv;
    }
}

// ---------------------------------------------------------------------------
extern "C" void kernel_launch(void* const* d_in, const int* in_sizes, int n_in,
                              void* d_out, int out_size)
{
    const float* vis  = (const float*)d_in[0];
    const float* lang = (const float*)d_in[1];
    // d_in[2] = mask (unused)
    const float* Wq   = (const float*)d_in[3];
    const float* Wk   = (const float*)d_in[4];
    const float* Wv   = (const float*)d_in[5];
    const float* Wo   = (const float*)d_in[6];
    float* out = (float*)d_out;

    float *q, *ao, *op, *ml;
    __half *w16, *lang16, *ao16, *q16, *k16, *v16;
    uint32_t *v16p, *wqT, *woT;
    cudaGetSymbolAddress((void**)&q,      g_q);
    cudaGetSymbolAddress((void**)&ao,     g_ao);
    cudaGetSymbolAddress((void**)&w16,    g_w16);
    cudaGetSymbolAddress((void**)&lang16, g_lang16);
    cudaGetSymbolAddress((void**)&ao16,   g_ao16);
    cudaGetSymbolAddress((void**)&wqT,    g_wqT);
    cudaGetSymbolAddress((void**)&woT,    g_woT);
    cudaGetSymbolAddress((void**)&v16p,   g_v16p);
    cudaGetSymbolAddress((void**)&q16,    g_q16);
    cudaGetSymbolAddress((void**)&k16,    g_k16);
    cudaGetSymbolAddress((void**)&v16,    g_v16);
    cudaGetSymbolAddress((void**)&op,     g_op);
    cudaGetSymbolAddress((void**)&ml,     g_ml);

    cudaFuncSetAttribute(gemm_kv_f16, cudaFuncAttributeMaxDynamicSharedMemorySize,
                         KV_SMEM);
    cudaFuncSetAttribute(gemm_proj, cudaFuncAttributeMaxDynamicSharedMemorySize,
                         KV_SMEM);
    cudaFuncSetAttribute(attn_f16, cudaFuncAttributeMaxDynamicSharedMemorySize,
                         ATTN_SMEM);

    // fused prep + vis pack
    prep_all<<<4096, 256>>>(Wk, Wv, Wq, Wo, lang, w16, wqT, woT, lang16);
    prep_vis16<<<(int)(((long)B_ * (C_ / 2) * S_) / 256), 256>>>(vis, v16p);

    // q projection (fp16 mma) -> f32 q, then validated repack to q16
    gemm_proj<<<dim3(INNER / 128, (B_ * T_) / 128), 256, KV_SMEM>>>(lang16, wqT, q);
    prep_q16<<<B_ * T_ * INNER / 256, 256>>>(q, q16);

    // fused k+v projection (fp16 tensor cores, cp.async pipeline)
    gemm_kv_f16<<<dim3(S_ / 128, (2 * INNER) / 128, B_), 256, KV_SMEM>>>(w16, v16p, k16, v16);

    // flash attention (tensor cores, split-KV, cp.async) + combine + fp16 repack
    attn_f16<<<dim3(SPLIT, BH_), 128, ATTN_SMEM>>>(q16, k16, v16, op, ml);
    attn_combine<<<BH_, 128>>>(op, ml, ao);
    conv16<<<B_ * T_ * INNER / 256, 256>>>(ao, ao16);

    // output projection (fp16 mma) -> f32 out
    gemm_proj<<<dim3(C_ / 128, (B_ * T_) / 128), 256, KV_SMEM>>>(ao16, woT, out);
}